// round 1
// baseline (speedup 1.0000x reference)
#include <cuda_runtime.h>
#include <math.h>

#define B_ 4
#define W_ 1024
#define C_ 1024
#define H_ 16
#define D_ 64

// Static device scratch (allocation-free rule).
__device__ float g_q[B_ * H_ * W_ * D_];   // [b][h][w][d]
__device__ float g_k[B_ * H_ * W_ * D_];
__device__ float g_v[B_ * H_ * W_ * D_];
__device__ float g_av[B_ * W_ * C_];       // [b][w][c]

// ---------------------------------------------------------------------------
// GEMM: C[r][c] = sum_k A[r][k] * Bw[c][k] + bias[c]
// A: [4096][1024] row-major, Bw: [1024][1024] row-major (both K-contiguous).
// TGT 0/1/2: write to g_q/g_k/g_v in [b][h][w][d] layout.
// TGT 3:     A is g_av, write plain [r][c] to Cout.
// ---------------------------------------------------------------------------
#define GBM 128
#define GBN 128
#define GBK 8

template <int TGT>
__global__ __launch_bounds__(256) void gemm_nt(const float* __restrict__ A,
                                               const float* __restrict__ Bw,
                                               const float* __restrict__ bias,
                                               float* __restrict__ Cout) {
    __shared__ float As[GBK][GBM];
    __shared__ float Bs[GBK][GBN];
    const int K = 1024;
    const int N = 1024;
    int tid  = threadIdx.x;
    int row0 = blockIdx.y * GBM;
    int col0 = blockIdx.x * GBN;
    int ty = tid >> 4, tx = tid & 15;

    const float* Abase = (TGT == 3) ? (const float*)g_av : A;

    float acc[8][8];
#pragma unroll
    for (int i = 0; i < 8; i++)
#pragma unroll
        for (int j = 0; j < 8; j++) acc[i][j] = 0.f;

    int lm = tid >> 1;          // 0..127
    int lk = (tid & 1) * 4;     // 0 or 4
    const float* Ap = Abase + (size_t)(row0 + lm) * K + lk;
    const float* Bp = Bw    + (size_t)(col0 + lm) * K + lk;

    for (int k0 = 0; k0 < K; k0 += GBK) {
        float4 a4 = *(const float4*)(Ap + k0);
        float4 b4 = *(const float4*)(Bp + k0);
        __syncthreads();
        As[lk + 0][lm] = a4.x; As[lk + 1][lm] = a4.y;
        As[lk + 2][lm] = a4.z; As[lk + 3][lm] = a4.w;
        Bs[lk + 0][lm] = b4.x; Bs[lk + 1][lm] = b4.y;
        Bs[lk + 2][lm] = b4.z; Bs[lk + 3][lm] = b4.w;
        __syncthreads();
#pragma unroll
        for (int kk = 0; kk < GBK; kk++) {
            float a[8], b[8];
            *(float4*)&a[0] = *(const float4*)&As[kk][ty * 8];
            *(float4*)&a[4] = *(const float4*)&As[kk][ty * 8 + 4];
            *(float4*)&b[0] = *(const float4*)&Bs[kk][tx * 8];
            *(float4*)&b[4] = *(const float4*)&Bs[kk][tx * 8 + 4];
#pragma unroll
            for (int i = 0; i < 8; i++)
#pragma unroll
                for (int j = 0; j < 8; j++)
                    acc[i][j] = fmaf(a[i], b[j], acc[i][j]);
        }
    }

#pragma unroll
    for (int i = 0; i < 8; i++) {
        int r = row0 + ty * 8 + i;
#pragma unroll
        for (int j = 0; j < 8; j++) {
            int c = col0 + tx * 8 + j;
            float val = acc[i][j] + bias[c];
            if (TGT == 3) {
                Cout[(size_t)r * N + c] = val;
            } else {
                float* dst = (TGT == 0) ? g_q : (TGT == 1) ? g_k : g_v;
                int bb = r >> 10, w = r & 1023, h = c >> 6, d = c & 63;
                dst[(((size_t)(bb * H_ + h)) * W_ + w) * D_ + d] = val;
            }
        }
    }
}

// ---------------------------------------------------------------------------
// Fused flash attention per (b, h, 64-row w-tile).
// S[i][j] = ( Qw[i]·Ku[j] + Qu[j]·er[:, w0+i] ) / 32
// Online softmax over u; O += P @ Vu; av[b][w][h*64+d] = O/l.
// ---------------------------------------------------------------------------
__global__ __launch_bounds__(256) void attn_kernel(const float* __restrict__ er) {
    extern __shared__ float sm[];
    float* QwT = sm;            // [d][i]  (d-major)
    float* E   = sm + 4096;     // [d][i]  er[:, w0+i]
    float* KuT = sm + 8192;     // [d][j]
    float* QuT = sm + 12288;    // [d][j]
    float* Vu  = sm + 16384;    // [j][d]
    float* P   = sm + 20480;    // [i][j]

    int tid = threadIdx.x;
    int b = blockIdx.z, h = blockIdx.y;
    int w0 = blockIdx.x * 64;

    const float* qbh = g_q + ((size_t)(b * H_ + h)) * W_ * D_;
    const float* kbh = g_k + ((size_t)(b * H_ + h)) * W_ * D_;
    const float* vbh = g_v + ((size_t)(b * H_ + h)) * W_ * D_;

    int li = tid >> 2;           // 0..63
    int dq = (tid & 3) * 4;      // 0,4,8,12

    // Load Qw transposed and er columns once.
    {
        const float* src = qbh + (size_t)w0 * D_;
#pragma unroll
        for (int pp = 0; pp < 4; pp++) {
            int d0 = pp * 16 + dq;
            float4 v4 = *(const float4*)(src + li * D_ + d0);
            QwT[(d0 + 0) * 64 + li] = v4.x; QwT[(d0 + 1) * 64 + li] = v4.y;
            QwT[(d0 + 2) * 64 + li] = v4.z; QwT[(d0 + 3) * 64 + li] = v4.w;
        }
        for (int t = tid; t < 4096; t += 256) {
            int d = t >> 6, i2 = t & 63;
            E[t] = er[d * 1024 + w0 + i2];
        }
    }

    int ty = tid >> 4, tx = tid & 15;
    float m_[4], l_[4], o_[4][4];
#pragma unroll
    for (int ii = 0; ii < 4; ii++) {
        m_[ii] = -1e30f; l_[ii] = 0.f;
#pragma unroll
        for (int jj = 0; jj < 4; jj++) o_[ii][jj] = 0.f;
    }

    for (int u0 = 0; u0 < W_; u0 += 64) {
        __syncthreads();   // previous tile fully consumed
        {
            const float* ks = kbh + (size_t)u0 * D_;
            const float* qs = qbh + (size_t)u0 * D_;
#pragma unroll
            for (int pp = 0; pp < 4; pp++) {
                int d0 = pp * 16 + dq;
                float4 kv = *(const float4*)(ks + li * D_ + d0);
                KuT[(d0 + 0) * 64 + li] = kv.x; KuT[(d0 + 1) * 64 + li] = kv.y;
                KuT[(d0 + 2) * 64 + li] = kv.z; KuT[(d0 + 3) * 64 + li] = kv.w;
                float4 qv = *(const float4*)(qs + li * D_ + d0);
                QuT[(d0 + 0) * 64 + li] = qv.x; QuT[(d0 + 1) * 64 + li] = qv.y;
                QuT[(d0 + 2) * 64 + li] = qv.z; QuT[(d0 + 3) * 64 + li] = qv.w;
            }
            const float4* vs = (const float4*)(vbh + (size_t)u0 * D_);
            for (int t = tid; t < 1024; t += 256) ((float4*)Vu)[t] = vs[t];
        }
        __syncthreads();

        // S tile: dual 64-deep dot (qk + skew bias)
        float s[4][4];
#pragma unroll
        for (int ii = 0; ii < 4; ii++)
#pragma unroll
            for (int jj = 0; jj < 4; jj++) s[ii][jj] = 0.f;

#pragma unroll 8
        for (int d = 0; d < 64; d++) {
            float4 a  = *(const float4*)&QwT[d * 64 + ty * 4];
            float4 kb = *(const float4*)&KuT[d * 64 + tx * 4];
            float4 e4 = *(const float4*)&E[d * 64 + ty * 4];
            float4 qu = *(const float4*)&QuT[d * 64 + tx * 4];
            float av_[4] = {a.x, a.y, a.z, a.w};
            float ev_[4] = {e4.x, e4.y, e4.z, e4.w};
            float bv_[4] = {kb.x, kb.y, kb.z, kb.w};
            float uv_[4] = {qu.x, qu.y, qu.z, qu.w};
#pragma unroll
            for (int ii = 0; ii < 4; ii++)
#pragma unroll
                for (int jj = 0; jj < 4; jj++)
                    s[ii][jj] = fmaf(av_[ii], bv_[jj],
                                fmaf(uv_[jj], ev_[ii], s[ii][jj]));
        }

        // scale 1/sqrt(1024)
#pragma unroll
        for (int ii = 0; ii < 4; ii++)
#pragma unroll
            for (int jj = 0; jj < 4; jj++) s[ii][jj] *= 0.03125f;

        // online softmax (rows shared across the 16 tx-lanes of a half-warp)
#pragma unroll
        for (int ii = 0; ii < 4; ii++) {
            float rmax = fmaxf(fmaxf(s[ii][0], s[ii][1]), fmaxf(s[ii][2], s[ii][3]));
#pragma unroll
            for (int off = 1; off < 16; off <<= 1)
                rmax = fmaxf(rmax, __shfl_xor_sync(0xffffffffu, rmax, off));
            float mnew = fmaxf(m_[ii], rmax);
            float corr = __expf(m_[ii] - mnew);
            m_[ii] = mnew;
            l_[ii] *= corr;
#pragma unroll
            for (int jj = 0; jj < 4; jj++) o_[ii][jj] *= corr;
            float rs = 0.f;
#pragma unroll
            for (int jj = 0; jj < 4; jj++) {
                s[ii][jj] = __expf(s[ii][jj] - mnew);
                rs += s[ii][jj];
            }
#pragma unroll
            for (int off = 1; off < 16; off <<= 1)
                rs += __shfl_xor_sync(0xffffffffu, rs, off);
            l_[ii] += rs;
        }

        // P to smem, then O += P @ Vu
#pragma unroll
        for (int ii = 0; ii < 4; ii++)
#pragma unroll
            for (int jj = 0; jj < 4; jj++)
                P[(ty * 4 + ii) * 64 + tx * 4 + jj] = s[ii][jj];
        __syncthreads();

#pragma unroll 4
        for (int j = 0; j < 64; j++) {
            float4 vv = *(const float4*)&Vu[j * 64 + tx * 4];
#pragma unroll
            for (int ii = 0; ii < 4; ii++) {
                float p = P[(ty * 4 + ii) * 64 + j];
                o_[ii][0] = fmaf(p, vv.x, o_[ii][0]);
                o_[ii][1] = fmaf(p, vv.y, o_[ii][1]);
                o_[ii][2] = fmaf(p, vv.z, o_[ii][2]);
                o_[ii][3] = fmaf(p, vv.w, o_[ii][3]);
            }
        }
    }

    // epilogue: normalize, write av in [b][w][c]
#pragma unroll
    for (int ii = 0; ii < 4; ii++) {
        float inv = 1.f / l_[ii];
        int w = w0 + ty * 4 + ii;
#pragma unroll
        for (int jj = 0; jj < 4; jj++) {
            g_av[((size_t)b * W_ + w) * C_ + h * 64 + tx * 4 + jj] = o_[ii][jj] * inv;
        }
    }
}

// ---------------------------------------------------------------------------
extern "C" void kernel_launch(void* const* d_in, const int* in_sizes, int n_in,
                              void* d_out, int out_size) {
    const float* x  = (const float*)d_in[0];
    const float* Wq = (const float*)d_in[1];
    const float* bq = (const float*)d_in[2];
    const float* Wk = (const float*)d_in[3];
    const float* bk = (const float*)d_in[4];
    const float* Wv = (const float*)d_in[5];
    const float* bv = (const float*)d_in[6];
    const float* Wo = (const float*)d_in[7];
    const float* bo = (const float*)d_in[8];
    const float* er = (const float*)d_in[9];
    float* out = (float*)d_out;

    dim3 g(1024 / GBN, 4096 / GBM);   // (8, 32)
    gemm_nt<0><<<g, 256>>>(x, Wq, bq, nullptr);
    gemm_nt<1><<<g, 256>>>(x, Wk, bk, nullptr);
    gemm_nt<2><<<g, 256>>>(x, Wv, bv, nullptr);

    cudaFuncSetAttribute(attn_kernel,
                         cudaFuncAttributeMaxDynamicSharedMemorySize, 96 * 1024);
    attn_kernel<<<dim3(16, 16, 4), 256, 96 * 1024>>>(er);

    gemm_nt<3><<<g, 256>>>(nullptr, Wo, bo, out);
}

// round 3
// speedup vs baseline: 1.0095x; 1.0095x over previous
#include <cuda_runtime.h>
#include <cstdint>
#include <math.h>

#define B_ 4
#define W_ 1024
#define C_ 1024
#define H_ 16
#define D_ 64

// Static device scratch (allocation-free rule).
__device__ float g_q[B_ * H_ * W_ * D_];   // [b][h][w][d]
__device__ float g_k[B_ * H_ * W_ * D_];
__device__ float g_v[B_ * H_ * W_ * D_];
__device__ float g_av[B_ * W_ * C_];       // [b][w][c]

// ---------------------------------------------------------------------------
// helpers
// ---------------------------------------------------------------------------
__device__ __forceinline__ uint32_t smem_to_u32(const void* p) {
    uint32_t a;
    asm("{ .reg .u64 t; cvta.to.shared.u64 t, %1; cvt.u32.u64 %0, t; }"
        : "=r"(a) : "l"(p));
    return a;
}
__device__ __forceinline__ void cp_async16(uint32_t s, const void* g) {
    asm volatile("cp.async.cg.shared.global [%0], [%1], 16;" :: "r"(s), "l"(g));
}
#define CP_COMMIT() asm volatile("cp.async.commit_group;" ::: "memory")
#define CP_WAIT(n)  asm volatile("cp.async.wait_group %0;" :: "n"(n) : "memory")

#define LDSM_X4(r0, r1, r2, r3, addr) \
    asm volatile("ldmatrix.sync.aligned.m8n8.x4.shared.b16 {%0,%1,%2,%3}, [%4];" \
        : "=r"(r0), "=r"(r1), "=r"(r2), "=r"(r3) : "r"(addr))

__device__ __forceinline__ uint32_t f2tf32(uint32_t x) {
    uint32_t r;
    asm("cvt.rn.tf32.f32 %0, %1;" : "=r"(r) : "r"(x));
    return r;
}
__device__ __forceinline__ void mma_tf32(float* c, const uint32_t* a,
                                         uint32_t b0, uint32_t b1) {
    asm volatile(
        "mma.sync.aligned.m16n8k8.row.col.f32.tf32.tf32.f32 "
        "{%0,%1,%2,%3}, {%4,%5,%6,%7}, {%8,%9}, {%0,%1,%2,%3};"
        : "+f"(c[0]), "+f"(c[1]), "+f"(c[2]), "+f"(c[3])
        : "r"(a[0]), "r"(a[1]), "r"(a[2]), "r"(a[3]), "r"(b0), "r"(b1));
}

// ---------------------------------------------------------------------------
// tf32 mma.sync GEMM: C[r][c] = sum_k A[r][k]*Bw[c][k] + bias[c]
// 128x128x32 tiles, 3-stage cp.async pipeline, swizzled smem + ldmatrix.
// TGT 0/1/2 scatter into g_q/g_k/g_v [b][h][w][d]; TGT 3 writes [r][c] to Cout.
// ---------------------------------------------------------------------------
#define STAGE_BYTES 32768            // 16KB A + 16KB B
#define GEMM_SMEM   (3 * STAGE_BYTES)

template <int TGT>
__global__ __launch_bounds__(256) void gemm_mma(const float* __restrict__ A,
                                                const float* __restrict__ Bw,
                                                const float* __restrict__ bias,
                                                float* __restrict__ Cout) {
    extern __shared__ char smem[];
    const uint32_t sb = smem_to_u32(smem);
    const int tid = threadIdx.x;
    const int lane = tid & 31;
    const int wid = tid >> 5;
    const int wm = wid & 1;          // 2 warps along M (64 rows each)
    const int wn = wid >> 1;         // 4 warps along N (32 cols each)
    const int row0 = blockIdx.y * 128;
    const int col0 = blockIdx.x * 128;
    const float* Abase = (TGT == 3) ? (const float*)g_av : A;

    // prefetch lane mapping: each thread copies 4x16B of A and 4x16B of B
    const int pr = tid >> 1;               // row 0..127
    const int pc = (tid & 1) * 4;          // chunk base 0 or 4 (16B chunks)
    const float* gA = Abase + (size_t)(row0 + pr) * 1024 + pc * 4;
    const float* gB = Bw    + (size_t)(col0 + pr) * 1024 + pc * 4;

    auto prefetch = [&](int stage, int ch) {
        uint32_t sa = sb + stage * STAGE_BYTES + pr * 128;
        uint32_t sbb = sa + 16384;
        const float* ga = gA + ch * 32;
        const float* gb = gB + ch * 32;
#pragma unroll
        for (int i = 0; i < 4; i++) {
            int c = pc + i;
            uint32_t ph = (uint32_t)((c ^ (pr & 7)) * 16);
            cp_async16(sa + ph, ga + i * 4);
            cp_async16(sbb + ph, gb + i * 4);
        }
    };

    float acc[4][4][4];
#pragma unroll
    for (int mt = 0; mt < 4; mt++)
#pragma unroll
        for (int nt = 0; nt < 4; nt++)
#pragma unroll
            for (int i = 0; i < 4; i++) acc[mt][nt][i] = 0.f;

    prefetch(0, 0); CP_COMMIT();
    prefetch(1, 1); CP_COMMIT();

    // ldmatrix lane addressing (row&7 == lane&7 for all our tiles)
    const int a_rowoff = (lane & 7) + ((lane >> 3) & 1) * 8;
    const int a_csel   = lane >> 4;                 // k-chunk lo/hi
    const int b_rowoff = ((lane >> 4) << 3) + (lane & 7);
    const int b_csel   = (lane >> 3) & 1;
    const uint32_t ph_xor = (uint32_t)(lane & 7);

    for (int ch = 0; ch < 32; ch++) {
        if (ch + 2 < 32) prefetch((ch + 2) % 3, ch + 2);
        CP_COMMIT();
        CP_WAIT(2);
        __syncthreads();

        const uint32_t ab = sb + (ch % 3) * STAGE_BYTES;
        const uint32_t bb = ab + 16384;
#pragma unroll
        for (int ks = 0; ks < 4; ks++) {
            uint32_t a[4][4];
#pragma unroll
            for (int mt = 0; mt < 4; mt++) {
                int row = wm * 64 + mt * 16 + a_rowoff;
                uint32_t ph = (uint32_t)((ks * 2 + a_csel) ^ ph_xor) * 16;
                LDSM_X4(a[mt][0], a[mt][1], a[mt][2], a[mt][3],
                        ab + row * 128 + ph);
#pragma unroll
                for (int i = 0; i < 4; i++) a[mt][i] = f2tf32(a[mt][i]);
            }
            uint32_t b[2][4];
#pragma unroll
            for (int nt2 = 0; nt2 < 2; nt2++) {
                int row = wn * 32 + nt2 * 16 + b_rowoff;
                uint32_t ph = (uint32_t)((ks * 2 + b_csel) ^ ph_xor) * 16;
                LDSM_X4(b[nt2][0], b[nt2][1], b[nt2][2], b[nt2][3],
                        bb + row * 128 + ph);
#pragma unroll
                for (int i = 0; i < 4; i++) b[nt2][i] = f2tf32(b[nt2][i]);
            }
#pragma unroll
            for (int mt = 0; mt < 4; mt++)
#pragma unroll
                for (int nt = 0; nt < 4; nt++)
                    mma_tf32(acc[mt][nt], a[mt],
                             b[nt >> 1][(nt & 1) * 2], b[nt >> 1][(nt & 1) * 2 + 1]);
        }
        __syncthreads();
    }

    // Epilogue: bias add + store (float2 per fragment row)
    const int g = lane >> 2;
    const int cpair = (lane & 3) * 2;
#pragma unroll
    for (int mt = 0; mt < 4; mt++) {
#pragma unroll
        for (int nt = 0; nt < 4; nt++) {
            int col = col0 + wn * 32 + nt * 8 + cpair;
            float2 bi = *(const float2*)(bias + col);
            int r0 = row0 + wm * 64 + mt * 16 + g;
            int r1 = r0 + 8;
            float2 v0 = make_float2(acc[mt][nt][0] + bi.x, acc[mt][nt][1] + bi.y);
            float2 v1 = make_float2(acc[mt][nt][2] + bi.x, acc[mt][nt][3] + bi.y);
            if (TGT == 3) {
                *(float2*)(Cout + (size_t)r0 * 1024 + col) = v0;
                *(float2*)(Cout + (size_t)r1 * 1024 + col) = v1;
            } else {
                float* dst = (TGT == 0) ? g_q : (TGT == 1) ? g_k : g_v;
                int h = col >> 6, d0 = col & 63;
                {
                    int bb2 = r0 >> 10, w = r0 & 1023;
                    *(float2*)(dst + (((size_t)(bb2 * H_ + h)) * W_ + w) * D_ + d0) = v0;
                }
                {
                    int bb2 = r1 >> 10, w = r1 & 1023;
                    *(float2*)(dst + (((size_t)(bb2 * H_ + h)) * W_ + w) * D_ + d0) = v1;
                }
            }
        }
    }
}

// ---------------------------------------------------------------------------
// Fused flash attention per (b, h, 64-row w-tile). (R1 version, passing)
// S[i][j] = ( Qw[i]·Ku[j] + Qu[j]·er[:, w0+i] ) / 32
// ---------------------------------------------------------------------------
__global__ __launch_bounds__(256) void attn_kernel(const float* __restrict__ er) {
    extern __shared__ float sm[];
    float* QwT = sm;            // [d][i]
    float* E   = sm + 4096;     // [d][i]
    float* KuT = sm + 8192;     // [d][j]
    float* QuT = sm + 12288;    // [d][j]
    float* Vu  = sm + 16384;    // [j][d]
    float* P   = sm + 20480;    // [i][j]

    int tid = threadIdx.x;
    int b = blockIdx.z, h = blockIdx.y;
    int w0 = blockIdx.x * 64;

    const float* qbh = g_q + ((size_t)(b * H_ + h)) * W_ * D_;
    const float* kbh = g_k + ((size_t)(b * H_ + h)) * W_ * D_;
    const float* vbh = g_v + ((size_t)(b * H_ + h)) * W_ * D_;

    int li = tid >> 2;
    int dq = (tid & 3) * 4;

    {
        const float* src = qbh + (size_t)w0 * D_;
#pragma unroll
        for (int pp = 0; pp < 4; pp++) {
            int d0 = pp * 16 + dq;
            float4 v4 = *(const float4*)(src + li * D_ + d0);
            QwT[(d0 + 0) * 64 + li] = v4.x; QwT[(d0 + 1) * 64 + li] = v4.y;
            QwT[(d0 + 2) * 64 + li] = v4.z; QwT[(d0 + 3) * 64 + li] = v4.w;
        }
        for (int t = tid; t < 4096; t += 256) {
            int d = t >> 6, i2 = t & 63;
            E[t] = er[d * 1024 + w0 + i2];
        }
    }

    int ty = tid >> 4, tx = tid & 15;
    float m_[4], l_[4], o_[4][4];
#pragma unroll
    for (int ii = 0; ii < 4; ii++) {
        m_[ii] = -1e30f; l_[ii] = 0.f;
#pragma unroll
        for (int jj = 0; jj < 4; jj++) o_[ii][jj] = 0.f;
    }

    for (int u0 = 0; u0 < W_; u0 += 64) {
        __syncthreads();
        {
            const float* ks = kbh + (size_t)u0 * D_;
            const float* qs = qbh + (size_t)u0 * D_;
#pragma unroll
            for (int pp = 0; pp < 4; pp++) {
                int d0 = pp * 16 + dq;
                float4 kv = *(const float4*)(ks + li * D_ + d0);
                KuT[(d0 + 0) * 64 + li] = kv.x; KuT[(d0 + 1) * 64 + li] = kv.y;
                KuT[(d0 + 2) * 64 + li] = kv.z; KuT[(d0 + 3) * 64 + li] = kv.w;
                float4 qv = *(const float4*)(qs + li * D_ + d0);
                QuT[(d0 + 0) * 64 + li] = qv.x; QuT[(d0 + 1) * 64 + li] = qv.y;
                QuT[(d0 + 2) * 64 + li] = qv.z; QuT[(d0 + 3) * 64 + li] = qv.w;
            }
            const float4* vs = (const float4*)(vbh + (size_t)u0 * D_);
            for (int t = tid; t < 1024; t += 256) ((float4*)Vu)[t] = vs[t];
        }
        __syncthreads();

        float s[4][4];
#pragma unroll
        for (int ii = 0; ii < 4; ii++)
#pragma unroll
            for (int jj = 0; jj < 4; jj++) s[ii][jj] = 0.f;

#pragma unroll 8
        for (int d = 0; d < 64; d++) {
            float4 a  = *(const float4*)&QwT[d * 64 + ty * 4];
            float4 kb = *(const float4*)&KuT[d * 64 + tx * 4];
            float4 e4 = *(const float4*)&E[d * 64 + ty * 4];
            float4 qu = *(const float4*)&QuT[d * 64 + tx * 4];
            float av_[4] = {a.x, a.y, a.z, a.w};
            float ev_[4] = {e4.x, e4.y, e4.z, e4.w};
            float bv_[4] = {kb.x, kb.y, kb.z, kb.w};
            float uv_[4] = {qu.x, qu.y, qu.z, qu.w};
#pragma unroll
            for (int ii = 0; ii < 4; ii++)
#pragma unroll
                for (int jj = 0; jj < 4; jj++)
                    s[ii][jj] = fmaf(av_[ii], bv_[jj],
                                fmaf(uv_[jj], ev_[ii], s[ii][jj]));
        }

#pragma unroll
        for (int ii = 0; ii < 4; ii++)
#pragma unroll
            for (int jj = 0; jj < 4; jj++) s[ii][jj] *= 0.03125f;

#pragma unroll
        for (int ii = 0; ii < 4; ii++) {
            float rmax = fmaxf(fmaxf(s[ii][0], s[ii][1]), fmaxf(s[ii][2], s[ii][3]));
#pragma unroll
            for (int off = 1; off < 16; off <<= 1)
                rmax = fmaxf(rmax, __shfl_xor_sync(0xffffffffu, rmax, off));
            float mnew = fmaxf(m_[ii], rmax);
            float corr = __expf(m_[ii] - mnew);
            m_[ii] = mnew;
            l_[ii] *= corr;
#pragma unroll
            for (int jj = 0; jj < 4; jj++) o_[ii][jj] *= corr;
            float rs = 0.f;
#pragma unroll
            for (int jj = 0; jj < 4; jj++) {
                s[ii][jj] = __expf(s[ii][jj] - mnew);
                rs += s[ii][jj];
            }
#pragma unroll
            for (int off = 1; off < 16; off <<= 1)
                rs += __shfl_xor_sync(0xffffffffu, rs, off);
            l_[ii] += rs;
        }

#pragma unroll
        for (int ii = 0; ii < 4; ii++)
#pragma unroll
            for (int jj = 0; jj < 4; jj++)
                P[(ty * 4 + ii) * 64 + tx * 4 + jj] = s[ii][jj];
        __syncthreads();

#pragma unroll 4
        for (int j = 0; j < 64; j++) {
            float4 vv = *(const float4*)&Vu[j * 64 + tx * 4];
#pragma unroll
            for (int ii = 0; ii < 4; ii++) {
                float p = P[(ty * 4 + ii) * 64 + j];
                o_[ii][0] = fmaf(p, vv.x, o_[ii][0]);
                o_[ii][1] = fmaf(p, vv.y, o_[ii][1]);
                o_[ii][2] = fmaf(p, vv.z, o_[ii][2]);
                o_[ii][3] = fmaf(p, vv.w, o_[ii][3]);
            }
        }
    }

#pragma unroll
    for (int ii = 0; ii < 4; ii++) {
        float inv = 1.f / l_[ii];
        int w = w0 + ty * 4 + ii;
#pragma unroll
        for (int jj = 0; jj < 4; jj++) {
            g_av[((size_t)b * W_ + w) * C_ + h * 64 + tx * 4 + jj] = o_[ii][jj] * inv;
        }
    }
}

// ---------------------------------------------------------------------------
extern "C" void kernel_launch(void* const* d_in, const int* in_sizes, int n_in,
                              void* d_out, int out_size) {
    const float* x  = (const float*)d_in[0];
    const float* Wq = (const float*)d_in[1];
    const float* bq = (const float*)d_in[2];
    const float* Wk = (const float*)d_in[3];
    const float* bk = (const float*)d_in[4];
    const float* Wv = (const float*)d_in[5];
    const float* bv = (const float*)d_in[6];
    const float* Wo = (const float*)d_in[7];
    const float* bo = (const float*)d_in[8];
    const float* er = (const float*)d_in[9];
    float* out = (float*)d_out;

    cudaFuncSetAttribute(gemm_mma<0>, cudaFuncAttributeMaxDynamicSharedMemorySize, GEMM_SMEM);
    cudaFuncSetAttribute(gemm_mma<1>, cudaFuncAttributeMaxDynamicSharedMemorySize, GEMM_SMEM);
    cudaFuncSetAttribute(gemm_mma<2>, cudaFuncAttributeMaxDynamicSharedMemorySize, GEMM_SMEM);
    cudaFuncSetAttribute(gemm_mma<3>, cudaFuncAttributeMaxDynamicSharedMemorySize, GEMM_SMEM);

    dim3 g(1024 / 128, 4096 / 128);   // (8, 32)
    gemm_mma<0><<<g, 256, GEMM_SMEM>>>(x, Wq, bq, nullptr);
    gemm_mma<1><<<g, 256, GEMM_SMEM>>>(x, Wk, bk, nullptr);
    gemm_mma<2><<<g, 256, GEMM_SMEM>>>(x, Wv, bv, nullptr);

    cudaFuncSetAttribute(attn_kernel,
                         cudaFuncAttributeMaxDynamicSharedMemorySize, 96 * 1024);
    attn_kernel<<<dim3(16, 16, 4), 256, 96 * 1024>>>(er);

    gemm_mma<3><<<g, 256, GEMM_SMEM>>>(nullptr, Wo, bo, out);
}

// round 4
// speedup vs baseline: 1.4442x; 1.4307x over previous
#include <cuda_runtime.h>
#include <cuda_bf16.h>
#include <cstdint>
#include <math.h>

#define B_ 4
#define W_ 1024
#define C_ 1024
#define H_ 16
#define D_ 64

// Static device scratch (allocation-free rule).
__device__ float g_q[B_ * H_ * W_ * D_];   // [b][h][w][d]
__device__ float g_k[B_ * H_ * W_ * D_];
__device__ float g_v[B_ * H_ * W_ * D_];
__device__ float g_av[B_ * W_ * C_];       // [b][w][c]

// ---------------------------------------------------------------------------
// helpers
// ---------------------------------------------------------------------------
__device__ __forceinline__ uint32_t smem_to_u32(const void* p) {
    uint32_t a;
    asm("{ .reg .u64 t; cvta.to.shared.u64 t, %1; cvt.u32.u64 %0, t; }"
        : "=r"(a) : "l"(p));
    return a;
}
#define LDSM_X4(r0, r1, r2, r3, addr) \
    asm volatile("ldmatrix.sync.aligned.m8n8.x4.shared.b16 {%0,%1,%2,%3}, [%4];" \
        : "=r"(r0), "=r"(r1), "=r"(r2), "=r"(r3) : "r"(addr))

__device__ __forceinline__ void mma_bf16(float* c, const uint32_t* a,
                                         uint32_t b0, uint32_t b1) {
    asm volatile(
        "mma.sync.aligned.m16n8k16.row.col.f32.bf16.bf16.f32 "
        "{%0,%1,%2,%3}, {%4,%5,%6,%7}, {%8,%9}, {%0,%1,%2,%3};"
        : "+f"(c[0]), "+f"(c[1]), "+f"(c[2]), "+f"(c[3])
        : "r"(a[0]), "r"(a[1]), "r"(a[2]), "r"(a[3]), "r"(b0), "r"(b1));
}
__device__ __forceinline__ uint32_t pkb(__nv_bfloat16 a, __nv_bfloat16 b) {
    __nv_bfloat162 t; t.x = a; t.y = b;
    return *(uint32_t*)&t;
}
// Convert 8 consecutive floats (2 float4) into hi/lo bf16 16B chunks.
__device__ __forceinline__ void cvt_hl(const float4& f0, const float4& f1,
                                       uint4& h, uint4& l) {
    __nv_bfloat16 h0 = __float2bfloat16_rn(f0.x), h1 = __float2bfloat16_rn(f0.y);
    __nv_bfloat16 h2 = __float2bfloat16_rn(f0.z), h3 = __float2bfloat16_rn(f0.w);
    __nv_bfloat16 h4 = __float2bfloat16_rn(f1.x), h5 = __float2bfloat16_rn(f1.y);
    __nv_bfloat16 h6 = __float2bfloat16_rn(f1.z), h7 = __float2bfloat16_rn(f1.w);
    h.x = pkb(h0, h1); h.y = pkb(h2, h3); h.z = pkb(h4, h5); h.w = pkb(h6, h7);
    float r0 = f0.x - __bfloat162float(h0), r1 = f0.y - __bfloat162float(h1);
    float r2 = f0.z - __bfloat162float(h2), r3 = f0.w - __bfloat162float(h3);
    float r4 = f1.x - __bfloat162float(h4), r5 = f1.y - __bfloat162float(h5);
    float r6 = f1.z - __bfloat162float(h6), r7 = f1.w - __bfloat162float(h7);
    l.x = pkb(__float2bfloat16_rn(r0), __float2bfloat16_rn(r1));
    l.y = pkb(__float2bfloat16_rn(r2), __float2bfloat16_rn(r3));
    l.z = pkb(__float2bfloat16_rn(r4), __float2bfloat16_rn(r5));
    l.w = pkb(__float2bfloat16_rn(r6), __float2bfloat16_rn(r7));
}

// ---------------------------------------------------------------------------
// bf16 split-precision mma GEMM: C[r][c] = sum_k A[r][k]*Bw[c][k] + bias[c]
// acc = Ahi*Bhi + Ahi*Blo + Alo*Bhi  (fp32 accumulate)  — error ~2^-17.
// 128x128x32 tiles, double-buffered smem, register-staged gmem loads.
// smem row (128B): [hi k0-7 | hi k8-15 | hi k16-23 | hi k24-31 | lo ...]
//   as 8 x 16B chunks, chunk phys = c ^ (row & 7)  (conflict-free ldmatrix).
// ---------------------------------------------------------------------------
#define GS_STAGE 32768               // A planes 16KB + B planes 16KB
#define GEMM_SMEM (2 * GS_STAGE)     // 64KB

template <int TGT>
__global__ __launch_bounds__(256) void gemm_bf16s(const float* __restrict__ A,
                                                  const float* __restrict__ Bw,
                                                  const float* __restrict__ bias,
                                                  float* __restrict__ Cout) {
    extern __shared__ char smem[];
    const uint32_t sb = smem_to_u32(smem);
    const int tid = threadIdx.x;
    const int lane = tid & 31;
    const int wid = tid >> 5;
    const int wm = wid & 1;          // 2 warps along M (64 rows each)
    const int wn = wid >> 1;         // 4 warps along N (32 cols each)
    const int row0 = blockIdx.y * 128;
    const int col0 = blockIdx.x * 128;
    const float* Abase = (TGT == 3) ? (const float*)g_av : A;

    const int pr  = tid >> 1;        // row 0..127
    const int pcb = tid & 1;         // 0: k0-15, 1: k16-31
    const float* gA = Abase + (size_t)(row0 + pr) * 1024 + pcb * 16;
    const float* gB = Bw    + (size_t)(col0 + pr) * 1024 + pcb * 16;

    float4 ra[4], rb[4];
    auto load_regs = [&](int ch) {
        const float* a = gA + ch * 32;
        const float* b = gB + ch * 32;
#pragma unroll
        for (int i = 0; i < 4; i++) {
            ra[i] = *(const float4*)(a + i * 4);
            rb[i] = *(const float4*)(b + i * 4);
        }
    };
    auto store_stage = [&](int buf) {
        char* abase = smem + buf * GS_STAGE + pr * 128;
        char* bbase = abase + 16384;
#pragma unroll
        for (int c = 0; c < 2; c++) {
            int chi = pcb * 2 + c;           // hi chunk 0..3
            int clo = 4 + chi;               // lo chunk 4..7
            uint4 h, l;
            cvt_hl(ra[2 * c], ra[2 * c + 1], h, l);
            *(uint4*)(abase + ((chi ^ (pr & 7)) * 16)) = h;
            *(uint4*)(abase + ((clo ^ (pr & 7)) * 16)) = l;
            cvt_hl(rb[2 * c], rb[2 * c + 1], h, l);
            *(uint4*)(bbase + ((chi ^ (pr & 7)) * 16)) = h;
            *(uint4*)(bbase + ((clo ^ (pr & 7)) * 16)) = l;
        }
    };

    float acc[4][4][4];
#pragma unroll
    for (int mt = 0; mt < 4; mt++)
#pragma unroll
        for (int nt = 0; nt < 4; nt++)
#pragma unroll
            for (int i = 0; i < 4; i++) acc[mt][nt][i] = 0.f;

    // ldmatrix lane addressing (row&7 == lane&7 for all mats)
    const int a_rowoff = (lane & 7) + ((lane >> 3) & 1) * 8;
    const int a_csel   = lane >> 4;
    const int b_rowoff = ((lane >> 4) << 3) + (lane & 7);
    const int b_csel   = (lane >> 3) & 1;
    const uint32_t lx = (uint32_t)(lane & 7);

    auto do_mma = [&](int buf) {
        const uint32_t ab = sb + buf * GS_STAGE;
        const uint32_t bb = ab + 16384;
#pragma unroll
        for (int ks = 0; ks < 2; ks++) {
            uint32_t ah[4][4], al[4][4], bh[2][4], bl[2][4];
#pragma unroll
            for (int mt = 0; mt < 4; mt++) {
                int row = wm * 64 + mt * 16 + a_rowoff;
                uint32_t ph = (uint32_t)((ks * 2 + a_csel) ^ lx) * 16;
                LDSM_X4(ah[mt][0], ah[mt][1], ah[mt][2], ah[mt][3],
                        ab + row * 128 + ph);
            }
#pragma unroll
            for (int n2 = 0; n2 < 2; n2++) {
                int row = wn * 32 + n2 * 16 + b_rowoff;
                uint32_t ph = (uint32_t)((ks * 2 + b_csel) ^ lx) * 16;
                LDSM_X4(bh[n2][0], bh[n2][1], bh[n2][2], bh[n2][3],
                        bb + row * 128 + ph);
            }
#pragma unroll
            for (int mt = 0; mt < 4; mt++)
#pragma unroll
                for (int nt = 0; nt < 4; nt++)
                    mma_bf16(acc[mt][nt], ah[mt],
                             bh[nt >> 1][(nt & 1) * 2], bh[nt >> 1][(nt & 1) * 2 + 1]);
            // B lo
#pragma unroll
            for (int n2 = 0; n2 < 2; n2++) {
                int row = wn * 32 + n2 * 16 + b_rowoff;
                uint32_t ph = (uint32_t)((4 + ks * 2 + b_csel) ^ lx) * 16;
                LDSM_X4(bl[n2][0], bl[n2][1], bl[n2][2], bl[n2][3],
                        bb + row * 128 + ph);
            }
#pragma unroll
            for (int mt = 0; mt < 4; mt++)
#pragma unroll
                for (int nt = 0; nt < 4; nt++)
                    mma_bf16(acc[mt][nt], ah[mt],
                             bl[nt >> 1][(nt & 1) * 2], bl[nt >> 1][(nt & 1) * 2 + 1]);
            // A lo
#pragma unroll
            for (int mt = 0; mt < 4; mt++) {
                int row = wm * 64 + mt * 16 + a_rowoff;
                uint32_t ph = (uint32_t)((4 + ks * 2 + a_csel) ^ lx) * 16;
                LDSM_X4(al[mt][0], al[mt][1], al[mt][2], al[mt][3],
                        ab + row * 128 + ph);
            }
#pragma unroll
            for (int mt = 0; mt < 4; mt++)
#pragma unroll
                for (int nt = 0; nt < 4; nt++)
                    mma_bf16(acc[mt][nt], al[mt],
                             bh[nt >> 1][(nt & 1) * 2], bh[nt >> 1][(nt & 1) * 2 + 1]);
        }
    };

    load_regs(0);
    store_stage(0);
    load_regs(1);
    __syncthreads();
    for (int ch = 0; ch < 32; ch++) {
        if (ch + 1 < 32) store_stage((ch + 1) & 1);
        if (ch + 2 < 32) load_regs(ch + 2);
        do_mma(ch & 1);
        __syncthreads();
    }

    // Epilogue: bias add + store (float2 per fragment row)
    const int g = lane >> 2;
    const int cpair = (lane & 3) * 2;
#pragma unroll
    for (int mt = 0; mt < 4; mt++) {
#pragma unroll
        for (int nt = 0; nt < 4; nt++) {
            int col = col0 + wn * 32 + nt * 8 + cpair;
            float2 bi = *(const float2*)(bias + col);
            int r0 = row0 + wm * 64 + mt * 16 + g;
            int r1 = r0 + 8;
            float2 v0 = make_float2(acc[mt][nt][0] + bi.x, acc[mt][nt][1] + bi.y);
            float2 v1 = make_float2(acc[mt][nt][2] + bi.x, acc[mt][nt][3] + bi.y);
            if (TGT == 3) {
                *(float2*)(Cout + (size_t)r0 * 1024 + col) = v0;
                *(float2*)(Cout + (size_t)r1 * 1024 + col) = v1;
            } else {
                float* dst = (TGT == 0) ? g_q : (TGT == 1) ? g_k : g_v;
                int h = col >> 6, d0 = col & 63;
                {
                    int bb2 = r0 >> 10, w = r0 & 1023;
                    *(float2*)(dst + (((size_t)(bb2 * H_ + h)) * W_ + w) * D_ + d0) = v0;
                }
                {
                    int bb2 = r1 >> 10, w = r1 & 1023;
                    *(float2*)(dst + (((size_t)(bb2 * H_ + h)) * W_ + w) * D_ + d0) = v1;
                }
            }
        }
    }
}

// ---------------------------------------------------------------------------
// Fused flash attention per (b, h, 64-row w-tile). (R1 version, passing)
// S[i][j] = ( Qw[i]·Ku[j] + Qu[j]·er[:, w0+i] ) / 32
// ---------------------------------------------------------------------------
__global__ __launch_bounds__(256) void attn_kernel(const float* __restrict__ er) {
    extern __shared__ float sm[];
    float* QwT = sm;            // [d][i]
    float* E   = sm + 4096;     // [d][i]
    float* KuT = sm + 8192;     // [d][j]
    float* QuT = sm + 12288;    // [d][j]
    float* Vu  = sm + 16384;    // [j][d]
    float* P   = sm + 20480;    // [i][j]

    int tid = threadIdx.x;
    int b = blockIdx.z, h = blockIdx.y;
    int w0 = blockIdx.x * 64;

    const float* qbh = g_q + ((size_t)(b * H_ + h)) * W_ * D_;
    const float* kbh = g_k + ((size_t)(b * H_ + h)) * W_ * D_;
    const float* vbh = g_v + ((size_t)(b * H_ + h)) * W_ * D_;

    int li = tid >> 2;
    int dq = (tid & 3) * 4;

    {
        const float* src = qbh + (size_t)w0 * D_;
#pragma unroll
        for (int pp = 0; pp < 4; pp++) {
            int d0 = pp * 16 + dq;
            float4 v4 = *(const float4*)(src + li * D_ + d0);
            QwT[(d0 + 0) * 64 + li] = v4.x; QwT[(d0 + 1) * 64 + li] = v4.y;
            QwT[(d0 + 2) * 64 + li] = v4.z; QwT[(d0 + 3) * 64 + li] = v4.w;
        }
        for (int t = tid; t < 4096; t += 256) {
            int d = t >> 6, i2 = t & 63;
            E[t] = er[d * 1024 + w0 + i2];
        }
    }

    int ty = tid >> 4, tx = tid & 15;
    float m_[4], l_[4], o_[4][4];
#pragma unroll
    for (int ii = 0; ii < 4; ii++) {
        m_[ii] = -1e30f; l_[ii] = 0.f;
#pragma unroll
        for (int jj = 0; jj < 4; jj++) o_[ii][jj] = 0.f;
    }

    for (int u0 = 0; u0 < W_; u0 += 64) {
        __syncthreads();
        {
            const float* ks = kbh + (size_t)u0 * D_;
            const float* qs = qbh + (size_t)u0 * D_;
#pragma unroll
            for (int pp = 0; pp < 4; pp++) {
                int d0 = pp * 16 + dq;
                float4 kv = *(const float4*)(ks + li * D_ + d0);
                KuT[(d0 + 0) * 64 + li] = kv.x; KuT[(d0 + 1) * 64 + li] = kv.y;
                KuT[(d0 + 2) * 64 + li] = kv.z; KuT[(d0 + 3) * 64 + li] = kv.w;
                float4 qv = *(const float4*)(qs + li * D_ + d0);
                QuT[(d0 + 0) * 64 + li] = qv.x; QuT[(d0 + 1) * 64 + li] = qv.y;
                QuT[(d0 + 2) * 64 + li] = qv.z; QuT[(d0 + 3) * 64 + li] = qv.w;
            }
            const float4* vs = (const float4*)(vbh + (size_t)u0 * D_);
            for (int t = tid; t < 1024; t += 256) ((float4*)Vu)[t] = vs[t];
        }
        __syncthreads();

        float s[4][4];
#pragma unroll
        for (int ii = 0; ii < 4; ii++)
#pragma unroll
            for (int jj = 0; jj < 4; jj++) s[ii][jj] = 0.f;

#pragma unroll 8
        for (int d = 0; d < 64; d++) {
            float4 a  = *(const float4*)&QwT[d * 64 + ty * 4];
            float4 kb = *(const float4*)&KuT[d * 64 + tx * 4];
            float4 e4 = *(const float4*)&E[d * 64 + ty * 4];
            float4 qu = *(const float4*)&QuT[d * 64 + tx * 4];
            float av_[4] = {a.x, a.y, a.z, a.w};
            float ev_[4] = {e4.x, e4.y, e4.z, e4.w};
            float bv_[4] = {kb.x, kb.y, kb.z, kb.w};
            float uv_[4] = {qu.x, qu.y, qu.z, qu.w};
#pragma unroll
            for (int ii = 0; ii < 4; ii++)
#pragma unroll
                for (int jj = 0; jj < 4; jj++)
                    s[ii][jj] = fmaf(av_[ii], bv_[jj],
                                fmaf(uv_[jj], ev_[ii], s[ii][jj]));
        }

#pragma unroll
        for (int ii = 0; ii < 4; ii++)
#pragma unroll
            for (int jj = 0; jj < 4; jj++) s[ii][jj] *= 0.03125f;

#pragma unroll
        for (int ii = 0; ii < 4; ii++) {
            float rmax = fmaxf(fmaxf(s[ii][0], s[ii][1]), fmaxf(s[ii][2], s[ii][3]));
#pragma unroll
            for (int off = 1; off < 16; off <<= 1)
                rmax = fmaxf(rmax, __shfl_xor_sync(0xffffffffu, rmax, off));
            float mnew = fmaxf(m_[ii], rmax);
            float corr = __expf(m_[ii] - mnew);
            m_[ii] = mnew;
            l_[ii] *= corr;
#pragma unroll
            for (int jj = 0; jj < 4; jj++) o_[ii][jj] *= corr;
            float rs = 0.f;
#pragma unroll
            for (int jj = 0; jj < 4; jj++) {
                s[ii][jj] = __expf(s[ii][jj] - mnew);
                rs += s[ii][jj];
            }
#pragma unroll
            for (int off = 1; off < 16; off <<= 1)
                rs += __shfl_xor_sync(0xffffffffu, rs, off);
            l_[ii] += rs;
        }

#pragma unroll
        for (int ii = 0; ii < 4; ii++)
#pragma unroll
            for (int jj = 0; jj < 4; jj++)
                P[(ty * 4 + ii) * 64 + tx * 4 + jj] = s[ii][jj];
        __syncthreads();

#pragma unroll 4
        for (int j = 0; j < 64; j++) {
            float4 vv = *(const float4*)&Vu[j * 64 + tx * 4];
#pragma unroll
            for (int ii = 0; ii < 4; ii++) {
                float p = P[(ty * 4 + ii) * 64 + j];
                o_[ii][0] = fmaf(p, vv.x, o_[ii][0]);
                o_[ii][1] = fmaf(p, vv.y, o_[ii][1]);
                o_[ii][2] = fmaf(p, vv.z, o_[ii][2]);
                o_[ii][3] = fmaf(p, vv.w, o_[ii][3]);
            }
        }
    }

#pragma unroll
    for (int ii = 0; ii < 4; ii++) {
        float inv = 1.f / l_[ii];
        int w = w0 + ty * 4 + ii;
#pragma unroll
        for (int jj = 0; jj < 4; jj++) {
            g_av[((size_t)b * W_ + w) * C_ + h * 64 + tx * 4 + jj] = o_[ii][jj] * inv;
        }
    }
}

// ---------------------------------------------------------------------------
extern "C" void kernel_launch(void* const* d_in, const int* in_sizes, int n_in,
                              void* d_out, int out_size) {
    const float* x  = (const float*)d_in[0];
    const float* Wq = (const float*)d_in[1];
    const float* bq = (const float*)d_in[2];
    const float* Wk = (const float*)d_in[3];
    const float* bk = (const float*)d_in[4];
    const float* Wv = (const float*)d_in[5];
    const float* bv = (const float*)d_in[6];
    const float* Wo = (const float*)d_in[7];
    const float* bo = (const float*)d_in[8];
    const float* er = (const float*)d_in[9];
    float* out = (float*)d_out;

    cudaFuncSetAttribute(gemm_bf16s<0>, cudaFuncAttributeMaxDynamicSharedMemorySize, GEMM_SMEM);
    cudaFuncSetAttribute(gemm_bf16s<1>, cudaFuncAttributeMaxDynamicSharedMemorySize, GEMM_SMEM);
    cudaFuncSetAttribute(gemm_bf16s<2>, cudaFuncAttributeMaxDynamicSharedMemorySize, GEMM_SMEM);
    cudaFuncSetAttribute(gemm_bf16s<3>, cudaFuncAttributeMaxDynamicSharedMemorySize, GEMM_SMEM);

    dim3 g(1024 / 128, 4096 / 128);   // (8, 32)
    gemm_bf16s<0><<<g, 256, GEMM_SMEM>>>(x, Wq, bq, nullptr);
    gemm_bf16s<1><<<g, 256, GEMM_SMEM>>>(x, Wk, bk, nullptr);
    gemm_bf16s<2><<<g, 256, GEMM_SMEM>>>(x, Wv, bv, nullptr);

    cudaFuncSetAttribute(attn_kernel,
                         cudaFuncAttributeMaxDynamicSharedMemorySize, 96 * 1024);
    attn_kernel<<<dim3(16, 16, 4), 256, 96 * 1024>>>(er);

    gemm_bf16s<3><<<g, 256, GEMM_SMEM>>>(nullptr, Wo, bo, out);
}

// round 6
// speedup vs baseline: 2.4755x; 1.7141x over previous
#include <cuda_runtime.h>
#include <cuda_bf16.h>
#include <cuda_fp16.h>
#include <cstdint>
#include <math.h>

#define B_ 4
#define W_ 1024
#define C_ 1024
#define H_ 16
#define D_ 64

// Static device scratch (allocation-free rule).
__device__ float g_q[B_ * H_ * W_ * D_];   // [b][h][w][d]
__device__ float g_k[B_ * H_ * W_ * D_];
__device__ float g_v[B_ * H_ * W_ * D_];
__device__ float g_av[B_ * W_ * C_];       // [b][w][c]

// ---------------------------------------------------------------------------
// helpers
// ---------------------------------------------------------------------------
__device__ __forceinline__ uint32_t smem_to_u32(const void* p) {
    uint32_t a;
    asm("{ .reg .u64 t; cvta.to.shared.u64 t, %1; cvt.u32.u64 %0, t; }"
        : "=r"(a) : "l"(p));
    return a;
}
#define LDSM_X4(r0, r1, r2, r3, addr) \
    asm volatile("ldmatrix.sync.aligned.m8n8.x4.shared.b16 {%0,%1,%2,%3}, [%4];" \
        : "=r"(r0), "=r"(r1), "=r"(r2), "=r"(r3) : "r"(addr))
#define LDSM_X4T(r0, r1, r2, r3, addr) \
    asm volatile("ldmatrix.sync.aligned.m8n8.x4.trans.shared.b16 {%0,%1,%2,%3}, [%4];" \
        : "=r"(r0), "=r"(r1), "=r"(r2), "=r"(r3) : "r"(addr))

__device__ __forceinline__ void mma_bf16(float* c, const uint32_t* a,
                                         uint32_t b0, uint32_t b1) {
    asm volatile(
        "mma.sync.aligned.m16n8k16.row.col.f32.bf16.bf16.f32 "
        "{%0,%1,%2,%3}, {%4,%5,%6,%7}, {%8,%9}, {%0,%1,%2,%3};"
        : "+f"(c[0]), "+f"(c[1]), "+f"(c[2]), "+f"(c[3])
        : "r"(a[0]), "r"(a[1]), "r"(a[2]), "r"(a[3]), "r"(b0), "r"(b1));
}
__device__ __forceinline__ void mma_f16(float* c, const uint32_t* a,
                                        uint32_t b0, uint32_t b1) {
    asm volatile(
        "mma.sync.aligned.m16n8k16.row.col.f32.f16.f16.f32 "
        "{%0,%1,%2,%3}, {%4,%5,%6,%7}, {%8,%9}, {%0,%1,%2,%3};"
        : "+f"(c[0]), "+f"(c[1]), "+f"(c[2]), "+f"(c[3])
        : "r"(a[0]), "r"(a[1]), "r"(a[2]), "r"(a[3]), "r"(b0), "r"(b1));
}
__device__ __forceinline__ uint32_t pkb(__nv_bfloat16 a, __nv_bfloat16 b) {
    __nv_bfloat162 t; t.x = a; t.y = b;
    return *(uint32_t*)&t;
}
__device__ __forceinline__ uint32_t pkh(float a, float b) {
    __half2 t = __floats2half2_rn(a, b);
    return *(uint32_t*)&t;
}
__device__ __forceinline__ uint4 pk8h(const float4& f0, const float4& f1) {
    uint4 r;
    r.x = pkh(f0.x, f0.y); r.y = pkh(f0.z, f0.w);
    r.z = pkh(f1.x, f1.y); r.w = pkh(f1.z, f1.w);
    return r;
}
// fp16 hi/lo split of 8 floats
__device__ __forceinline__ void cvt_hl16(const float4& f0, const float4& f1,
                                         uint4& h, uint4& l) {
    h = pk8h(f0, f1);
    const __half2* hp = (const __half2*)&h;
    float2 a0 = __half22float2(hp[0]), a1 = __half22float2(hp[1]);
    float2 a2 = __half22float2(hp[2]), a3 = __half22float2(hp[3]);
    float4 r0 = make_float4(f0.x - a0.x, f0.y - a0.y, f0.z - a1.x, f0.w - a1.y);
    float4 r1 = make_float4(f1.x - a2.x, f1.y - a2.y, f1.z - a3.x, f1.w - a3.y);
    l = pk8h(r0, r1);
}
// bf16 hi/lo split of 8 floats (GEMM path)
__device__ __forceinline__ void cvt_hl(const float4& f0, const float4& f1,
                                       uint4& h, uint4& l) {
    __nv_bfloat16 h0 = __float2bfloat16_rn(f0.x), h1 = __float2bfloat16_rn(f0.y);
    __nv_bfloat16 h2 = __float2bfloat16_rn(f0.z), h3 = __float2bfloat16_rn(f0.w);
    __nv_bfloat16 h4 = __float2bfloat16_rn(f1.x), h5 = __float2bfloat16_rn(f1.y);
    __nv_bfloat16 h6 = __float2bfloat16_rn(f1.z), h7 = __float2bfloat16_rn(f1.w);
    h.x = pkb(h0, h1); h.y = pkb(h2, h3); h.z = pkb(h4, h5); h.w = pkb(h6, h7);
    float r0 = f0.x - __bfloat162float(h0), r1 = f0.y - __bfloat162float(h1);
    float r2 = f0.z - __bfloat162float(h2), r3 = f0.w - __bfloat162float(h3);
    float r4 = f1.x - __bfloat162float(h4), r5 = f1.y - __bfloat162float(h5);
    float r6 = f1.z - __bfloat162float(h6), r7 = f1.w - __bfloat162float(h7);
    l.x = pkb(__float2bfloat16_rn(r0), __float2bfloat16_rn(r1));
    l.y = pkb(__float2bfloat16_rn(r2), __float2bfloat16_rn(r3));
    l.z = pkb(__float2bfloat16_rn(r4), __float2bfloat16_rn(r5));
    l.w = pkb(__float2bfloat16_rn(r6), __float2bfloat16_rn(r7));
}

// ---------------------------------------------------------------------------
// bf16 split-precision mma GEMM (unchanged from R4 — 3-pass hi/lo)
// ---------------------------------------------------------------------------
#define GS_STAGE 32768
#define GEMM_SMEM (2 * GS_STAGE)

template <int TGT>
__global__ __launch_bounds__(256) void gemm_bf16s(const float* __restrict__ A,
                                                  const float* __restrict__ Bw,
                                                  const float* __restrict__ bias,
                                                  float* __restrict__ Cout) {
    extern __shared__ char smem[];
    const uint32_t sb = smem_to_u32(smem);
    const int tid = threadIdx.x;
    const int lane = tid & 31;
    const int wid = tid >> 5;
    const int wm = wid & 1;
    const int wn = wid >> 1;
    const int row0 = blockIdx.y * 128;
    const int col0 = blockIdx.x * 128;
    const float* Abase = (TGT == 3) ? (const float*)g_av : A;

    const int pr  = tid >> 1;
    const int pcb = tid & 1;
    const float* gA = Abase + (size_t)(row0 + pr) * 1024 + pcb * 16;
    const float* gB = Bw    + (size_t)(col0 + pr) * 1024 + pcb * 16;

    float4 ra[4], rb[4];
    auto load_regs = [&](int ch) {
        const float* a = gA + ch * 32;
        const float* b = gB + ch * 32;
#pragma unroll
        for (int i = 0; i < 4; i++) {
            ra[i] = *(const float4*)(a + i * 4);
            rb[i] = *(const float4*)(b + i * 4);
        }
    };
    auto store_stage = [&](int buf) {
        char* abase = smem + buf * GS_STAGE + pr * 128;
        char* bbase = abase + 16384;
#pragma unroll
        for (int c = 0; c < 2; c++) {
            int chi = pcb * 2 + c;
            int clo = 4 + chi;
            uint4 h, l;
            cvt_hl(ra[2 * c], ra[2 * c + 1], h, l);
            *(uint4*)(abase + ((chi ^ (pr & 7)) * 16)) = h;
            *(uint4*)(abase + ((clo ^ (pr & 7)) * 16)) = l;
            cvt_hl(rb[2 * c], rb[2 * c + 1], h, l);
            *(uint4*)(bbase + ((chi ^ (pr & 7)) * 16)) = h;
            *(uint4*)(bbase + ((clo ^ (pr & 7)) * 16)) = l;
        }
    };

    float acc[4][4][4];
#pragma unroll
    for (int mt = 0; mt < 4; mt++)
#pragma unroll
        for (int nt = 0; nt < 4; nt++)
#pragma unroll
            for (int i = 0; i < 4; i++) acc[mt][nt][i] = 0.f;

    const int a_rowoff = (lane & 7) + ((lane >> 3) & 1) * 8;
    const int a_csel   = lane >> 4;
    const int b_rowoff = ((lane >> 4) << 3) + (lane & 7);
    const int b_csel   = (lane >> 3) & 1;
    const uint32_t lx = (uint32_t)(lane & 7);

    auto do_mma = [&](int buf) {
        const uint32_t ab = sb + buf * GS_STAGE;
        const uint32_t bb = ab + 16384;
#pragma unroll
        for (int ks = 0; ks < 2; ks++) {
            uint32_t ah[4][4], al[4][4], bh[2][4], bl[2][4];
#pragma unroll
            for (int mt = 0; mt < 4; mt++) {
                int row = wm * 64 + mt * 16 + a_rowoff;
                uint32_t ph = (uint32_t)((ks * 2 + a_csel) ^ lx) * 16;
                LDSM_X4(ah[mt][0], ah[mt][1], ah[mt][2], ah[mt][3],
                        ab + row * 128 + ph);
            }
#pragma unroll
            for (int n2 = 0; n2 < 2; n2++) {
                int row = wn * 32 + n2 * 16 + b_rowoff;
                uint32_t ph = (uint32_t)((ks * 2 + b_csel) ^ lx) * 16;
                LDSM_X4(bh[n2][0], bh[n2][1], bh[n2][2], bh[n2][3],
                        bb + row * 128 + ph);
            }
#pragma unroll
            for (int mt = 0; mt < 4; mt++)
#pragma unroll
                for (int nt = 0; nt < 4; nt++)
                    mma_bf16(acc[mt][nt], ah[mt],
                             bh[nt >> 1][(nt & 1) * 2], bh[nt >> 1][(nt & 1) * 2 + 1]);
#pragma unroll
            for (int n2 = 0; n2 < 2; n2++) {
                int row = wn * 32 + n2 * 16 + b_rowoff;
                uint32_t ph = (uint32_t)((4 + ks * 2 + b_csel) ^ lx) * 16;
                LDSM_X4(bl[n2][0], bl[n2][1], bl[n2][2], bl[n2][3],
                        bb + row * 128 + ph);
            }
#pragma unroll
            for (int mt = 0; mt < 4; mt++)
#pragma unroll
                for (int nt = 0; nt < 4; nt++)
                    mma_bf16(acc[mt][nt], ah[mt],
                             bl[nt >> 1][(nt & 1) * 2], bl[nt >> 1][(nt & 1) * 2 + 1]);
#pragma unroll
            for (int mt = 0; mt < 4; mt++) {
                int row = wm * 64 + mt * 16 + a_rowoff;
                uint32_t ph = (uint32_t)((4 + ks * 2 + a_csel) ^ lx) * 16;
                LDSM_X4(al[mt][0], al[mt][1], al[mt][2], al[mt][3],
                        ab + row * 128 + ph);
            }
#pragma unroll
            for (int mt = 0; mt < 4; mt++)
#pragma unroll
                for (int nt = 0; nt < 4; nt++)
                    mma_bf16(acc[mt][nt], al[mt],
                             bh[nt >> 1][(nt & 1) * 2], bh[nt >> 1][(nt & 1) * 2 + 1]);
        }
    };

    load_regs(0);
    store_stage(0);
    load_regs(1);
    __syncthreads();
    for (int ch = 0; ch < 32; ch++) {
        if (ch + 1 < 32) store_stage((ch + 1) & 1);
        if (ch + 2 < 32) load_regs(ch + 2);
        do_mma(ch & 1);
        __syncthreads();
    }

    const int g = lane >> 2;
    const int cpair = (lane & 3) * 2;
#pragma unroll
    for (int mt = 0; mt < 4; mt++) {
#pragma unroll
        for (int nt = 0; nt < 4; nt++) {
            int col = col0 + wn * 32 + nt * 8 + cpair;
            float2 bi = *(const float2*)(bias + col);
            int r0 = row0 + wm * 64 + mt * 16 + g;
            int r1 = r0 + 8;
            float2 v0 = make_float2(acc[mt][nt][0] + bi.x, acc[mt][nt][1] + bi.y);
            float2 v1 = make_float2(acc[mt][nt][2] + bi.x, acc[mt][nt][3] + bi.y);
            if (TGT == 3) {
                *(float2*)(Cout + (size_t)r0 * 1024 + col) = v0;
                *(float2*)(Cout + (size_t)r1 * 1024 + col) = v1;
            } else {
                float* dst = (TGT == 0) ? g_q : (TGT == 1) ? g_k : g_v;
                int h = col >> 6, d0 = col & 63;
                {
                    int bb2 = r0 >> 10, w = r0 & 1023;
                    *(float2*)(dst + (((size_t)(bb2 * H_ + h)) * W_ + w) * D_ + d0) = v0;
                }
                {
                    int bb2 = r1 >> 10, w = r1 & 1023;
                    *(float2*)(dst + (((size_t)(bb2 * H_ + h)) * W_ + w) * D_ + d0) = v1;
                }
            }
        }
    }
}

// ---------------------------------------------------------------------------
// Tensor-core flash attention. One CTA per (bh, 128-row w-tile); 8 warps,
// each warp owns 16 full rows.
// S[i][j] = ( Qw[i]·Ku[j] + E[i]·Qu[j] ) / 32,  E[i] = er[:, w0+i]
//  -> one fp16 mma GEMM with K=128: A = [Qw | E^T(trans)], B = [Ku | Qu].
// Online softmax in registers; O += P@V with 3-pass fp16 hi/lo split.
// smem: Qw fp16 [128i][64k]          @ 0      (16KB)
//       Et fp16 [64d][128i]          @ 16384  (16KB)
//       KQ fp16 [128j][128k]         @ 32768  (32KB)
//       Vhi fp16 [128u][64d]         @ 65536  (16KB)
//       Vlo fp16 [128u][64d]         @ 81920  (16KB)
// ---------------------------------------------------------------------------
#define ATTN_SMEM 98304

__global__ __launch_bounds__(256) void attn_mma(const float* __restrict__ er) {
    extern __shared__ char sm[];
    const uint32_t sb = smem_to_u32(sm);
    const int tid = threadIdx.x;
    const int lane = tid & 31;
    const int warp = tid >> 5;
    const int bh = blockIdx.y;
    const int b = bh >> 4, h = bh & 15;
    const int w0 = blockIdx.x * 128;

    const float* qbh = g_q + (size_t)bh * W_ * D_;
    const float* kbh = g_k + (size_t)bh * W_ * D_;
    const float* vbh = g_v + (size_t)bh * W_ * D_;

    // ---- load Qw tile (once): rows i, 64 fp16 = 128B/row, swizzled
    {
        int i = tid >> 1, part = tid & 1;
        const float* src = qbh + (size_t)(w0 + i) * 64 + part * 32;
#pragma unroll
        for (int cc = 0; cc < 4; cc++) {
            float4 f0 = *(const float4*)(src + cc * 8);
            float4 f1 = *(const float4*)(src + cc * 8 + 4);
            int chunk = part * 4 + cc;
            *(uint4*)(sm + i * 128 + ((chunk ^ (i & 7)) * 16)) = pk8h(f0, f1);
        }
    }
    // ---- load Et tile (once): Et[d][i] = er[d][w0+i]; rows 256B, swizzled
    for (int t = tid; t < 8192; t += 256) {
        int d = t >> 7, i = t & 127;
        float v = er[d * 1024 + w0 + i];
        int c16 = i >> 3;
        uint32_t addr = 16384u + d * 256 + ((c16 >> 3) * 128) +
                        (((c16 & 7) ^ (d & 7)) * 16) + ((i & 7) * 2);
        *(__half*)(sm + addr) = __float2half_rn(v);
    }

    // per-thread state
    float s[16][4];
    float o[8][4];
    float m0 = -1e30f, m1 = -1e30f, l0 = 0.f, l1 = 0.f;
#pragma unroll
    for (int nt = 0; nt < 8; nt++)
#pragma unroll
        for (int i = 0; i < 4; i++) o[nt][i] = 0.f;

    const int arow = (lane & 7) + ((lane >> 3) & 1) * 8;
    const int acs  = lane >> 4;
    const int brow = ((lane >> 4) << 3) + (lane & 7);
    const int bcs  = (lane >> 3) & 1;
    const int tm = lane >> 3, tr = lane & 7;
    const int i0 = warp * 16;

    for (int ch = 0; ch < 8; ch++) {
        __syncthreads();   // previous chunk fully consumed
        // ---- KQ tile: row j, k-half from K (part 0) or Q (part 1)
        {
            int j = tid >> 1, part = tid & 1;
            const float* src = (part ? qbh : kbh) + (size_t)(ch * 128 + j) * 64;
            char* dst = sm + 32768 + j * 256 + part * 128;
#pragma unroll
            for (int cc = 0; cc < 8; cc++) {
                float4 f0 = *(const float4*)(src + cc * 8);
                float4 f1 = *(const float4*)(src + cc * 8 + 4);
                *(uint4*)(dst + ((cc ^ (j & 7)) * 16)) = pk8h(f0, f1);
            }
        }
        // ---- V tile hi/lo
        {
            int u = tid >> 1, part = tid & 1;
            const float* src = vbh + (size_t)(ch * 128 + u) * 64 + part * 32;
#pragma unroll
            for (int cc = 0; cc < 4; cc++) {
                float4 f0 = *(const float4*)(src + cc * 8);
                float4 f1 = *(const float4*)(src + cc * 8 + 4);
                uint4 hh, ll;
                cvt_hl16(f0, f1, hh, ll);
                int chunk = part * 4 + cc;
                uint32_t off = u * 128 + ((chunk ^ (u & 7)) * 16);
                *(uint4*)(sm + 65536 + off) = hh;
                *(uint4*)(sm + 81920 + off) = ll;
            }
        }
        __syncthreads();

        // ---- S = [Qw|Et] @ [Ku|Qu]^T   (fp16, K=128)
#pragma unroll
        for (int nt = 0; nt < 16; nt++)
#pragma unroll
            for (int i = 0; i < 4; i++) s[nt][i] = 0.f;

#pragma unroll
        for (int kb = 0; kb < 8; kb++) {
            uint32_t a[4];
            if (kb < 4) {
                int row = i0 + arow;
                int chunk = kb * 2 + acs;
                LDSM_X4(a[0], a[1], a[2], a[3],
                        sb + row * 128 + ((chunk ^ (row & 7)) * 16));
            } else {
                // A-frag trans quadrants: matrix m -> (row = m&1, k = m>>1)
                int d = (kb - 4) * 16 + (tm >> 1) * 8 + tr;
                int icol = i0 + (tm & 1) * 8;
                int c16 = icol >> 3;
                LDSM_X4T(a[0], a[1], a[2], a[3],
                         sb + 16384 + d * 256 + ((c16 >> 3) * 128) +
                         (((c16 & 7) ^ (d & 7)) * 16));
            }
#pragma unroll
            for (int np = 0; np < 8; np++) {
                uint32_t b0, b1, b2, b3;
                int j = np * 16 + brow;
                int chunk = kb * 2 + bcs;
                LDSM_X4(b0, b1, b2, b3,
                        sb + 32768 + j * 256 + ((chunk >> 3) * 128) +
                        (((chunk & 7) ^ (j & 7)) * 16));
                mma_f16(s[2 * np], a, b0, b1);
                mma_f16(s[2 * np + 1], a, b2, b3);
            }
        }

        // ---- scale + online softmax (rows g = lane>>2 and g+8)
        float mr0 = -1e30f, mr1 = -1e30f;
#pragma unroll
        for (int nt = 0; nt < 16; nt++) {
            s[nt][0] *= 0.03125f; s[nt][1] *= 0.03125f;
            s[nt][2] *= 0.03125f; s[nt][3] *= 0.03125f;
            mr0 = fmaxf(mr0, fmaxf(s[nt][0], s[nt][1]));
            mr1 = fmaxf(mr1, fmaxf(s[nt][2], s[nt][3]));
        }
        mr0 = fmaxf(mr0, __shfl_xor_sync(0xffffffffu, mr0, 1));
        mr0 = fmaxf(mr0, __shfl_xor_sync(0xffffffffu, mr0, 2));
        mr1 = fmaxf(mr1, __shfl_xor_sync(0xffffffffu, mr1, 1));
        mr1 = fmaxf(mr1, __shfl_xor_sync(0xffffffffu, mr1, 2));
        float mn0 = fmaxf(m0, mr0), mn1 = fmaxf(m1, mr1);
        float c0 = __expf(m0 - mn0), c1 = __expf(m1 - mn1);
        m0 = mn0; m1 = mn1;
        l0 *= c0; l1 *= c1;
#pragma unroll
        for (int nt = 0; nt < 8; nt++) {
            o[nt][0] *= c0; o[nt][1] *= c0;
            o[nt][2] *= c1; o[nt][3] *= c1;
        }
        float rs0 = 0.f, rs1 = 0.f;
#pragma unroll
        for (int nt = 0; nt < 16; nt++) {
            s[nt][0] = __expf(s[nt][0] - mn0);
            s[nt][1] = __expf(s[nt][1] - mn0);
            s[nt][2] = __expf(s[nt][2] - mn1);
            s[nt][3] = __expf(s[nt][3] - mn1);
            rs0 += s[nt][0] + s[nt][1];
            rs1 += s[nt][2] + s[nt][3];
        }
        rs0 += __shfl_xor_sync(0xffffffffu, rs0, 1);
        rs0 += __shfl_xor_sync(0xffffffffu, rs0, 2);
        rs1 += __shfl_xor_sync(0xffffffffu, rs1, 1);
        rs1 += __shfl_xor_sync(0xffffffffu, rs1, 2);
        l0 += rs0; l1 += rs1;

        // ---- O += P @ V  (fp16, 3-pass hi/lo split)
#pragma unroll
        for (int kb = 0; kb < 8; kb++) {
            uint32_t ah[4], al[4];
            {
                float* p0 = s[2 * kb];
                float* p1 = s[2 * kb + 1];
                ah[0] = pkh(p0[0], p0[1]); ah[1] = pkh(p0[2], p0[3]);
                ah[2] = pkh(p1[0], p1[1]); ah[3] = pkh(p1[2], p1[3]);
#pragma unroll
                for (int r = 0; r < 4; r++) {
                    float2 hf = __half22float2(*(__half2*)&ah[r]);
                    float* ps = (r < 2) ? p0 : p1;
                    int c = (r & 1) * 2;
                    al[r] = pkh(ps[c] - hf.x, ps[c + 1] - hf.y);
                }
            }
            int u = kb * 16 + (tm & 1) * 8 + tr;
#pragma unroll
            for (int np = 0; np < 4; np++) {
                int d0 = np * 16 + (tm >> 1) * 8;
                int chunk = d0 >> 3;
                uint32_t off = u * 128 + ((chunk ^ (u & 7)) * 16);
                uint32_t vh0, vh1, vh2, vh3, vl0, vl1, vl2, vl3;
                LDSM_X4T(vh0, vh1, vh2, vh3, sb + 65536 + off);
                LDSM_X4T(vl0, vl1, vl2, vl3, sb + 81920 + off);
                mma_f16(o[2 * np], ah, vh0, vh1);
                mma_f16(o[2 * np + 1], ah, vh2, vh3);
                mma_f16(o[2 * np], al, vh0, vh1);
                mma_f16(o[2 * np + 1], al, vh2, vh3);
                mma_f16(o[2 * np], ah, vl0, vl1);
                mma_f16(o[2 * np + 1], ah, vl2, vl3);
            }
        }
    }

    // ---- epilogue: normalize, write av [b][w][h*64+d]
    float inv0 = 1.f / l0, inv1 = 1.f / l1;
    const int g = lane >> 2, cp = (lane & 3) * 2;
    const int wr = w0 + warp * 16 + g;
    float* obase = g_av + ((size_t)b * W_ + wr) * C_ + h * 64;
#pragma unroll
    for (int np = 0; np < 8; np++) {
        int d = np * 8 + cp;
        *(float2*)(obase + d) =
            make_float2(o[np][0] * inv0, o[np][1] * inv0);
        *(float2*)(obase + (size_t)8 * C_ + d) =
            make_float2(o[np][2] * inv1, o[np][3] * inv1);
    }
}

// ---------------------------------------------------------------------------
extern "C" void kernel_launch(void* const* d_in, const int* in_sizes, int n_in,
                              void* d_out, int out_size) {
    const float* x  = (const float*)d_in[0];
    const float* Wq = (const float*)d_in[1];
    const float* bq = (const float*)d_in[2];
    const float* Wk = (const float*)d_in[3];
    const float* bk = (const float*)d_in[4];
    const float* Wv = (const float*)d_in[5];
    const float* bv = (const float*)d_in[6];
    const float* Wo = (const float*)d_in[7];
    const float* bo = (const float*)d_in[8];
    const float* er = (const float*)d_in[9];
    float* out = (float*)d_out;

    cudaFuncSetAttribute(gemm_bf16s<0>, cudaFuncAttributeMaxDynamicSharedMemorySize, GEMM_SMEM);
    cudaFuncSetAttribute(gemm_bf16s<1>, cudaFuncAttributeMaxDynamicSharedMemorySize, GEMM_SMEM);
    cudaFuncSetAttribute(gemm_bf16s<2>, cudaFuncAttributeMaxDynamicSharedMemorySize, GEMM_SMEM);
    cudaFuncSetAttribute(gemm_bf16s<3>, cudaFuncAttributeMaxDynamicSharedMemorySize, GEMM_SMEM);
    cudaFuncSetAttribute(attn_mma, cudaFuncAttributeMaxDynamicSharedMemorySize, ATTN_SMEM);

    dim3 g(1024 / 128, 4096 / 128);   // (8, 32)
    gemm_bf16s<0><<<g, 256, GEMM_SMEM>>>(x, Wq, bq, nullptr);
    gemm_bf16s<1><<<g, 256, GEMM_SMEM>>>(x, Wk, bk, nullptr);
    gemm_bf16s<2><<<g, 256, GEMM_SMEM>>>(x, Wv, bv, nullptr);

    attn_mma<<<dim3(8, 64), 256, ATTN_SMEM>>>(er);

    gemm_bf16s<3><<<g, 256, GEMM_SMEM>>>(nullptr, Wo, bo, out);
}

// round 7
// speedup vs baseline: 2.9503x; 1.1918x over previous
#include <cuda_runtime.h>
#include <cuda_bf16.h>
#include <cuda_fp16.h>
#include <cstdint>
#include <math.h>

#define B_ 4
#define W_ 1024
#define C_ 1024
#define H_ 16
#define D_ 64

// Static device scratch (allocation-free rule).
__device__ __half g_qh[B_ * H_ * W_ * D_];   // [b][h][w][d] fp16
__device__ __half g_kh[B_ * H_ * W_ * D_];
__device__ __half g_vh[B_ * H_ * W_ * D_];   // V hi plane
__device__ __half g_vl[B_ * H_ * W_ * D_];   // V lo plane (residual)
__device__ float  g_av[B_ * W_ * C_];        // [b][w][c]

// ---------------------------------------------------------------------------
// helpers
// ---------------------------------------------------------------------------
__device__ __forceinline__ uint32_t smem_to_u32(const void* p) {
    uint32_t a;
    asm("{ .reg .u64 t; cvta.to.shared.u64 t, %1; cvt.u32.u64 %0, t; }"
        : "=r"(a) : "l"(p));
    return a;
}
__device__ __forceinline__ void cp_async16(uint32_t s, const void* g) {
    asm volatile("cp.async.cg.shared.global [%0], [%1], 16;" :: "r"(s), "l"(g));
}
#define CP_COMMIT() asm volatile("cp.async.commit_group;" ::: "memory")
#define CP_WAIT(n)  asm volatile("cp.async.wait_group %0;" :: "n"(n) : "memory")

#define LDSM_X4(r0, r1, r2, r3, addr) \
    asm volatile("ldmatrix.sync.aligned.m8n8.x4.shared.b16 {%0,%1,%2,%3}, [%4];" \
        : "=r"(r0), "=r"(r1), "=r"(r2), "=r"(r3) : "r"(addr))
#define LDSM_X4T(r0, r1, r2, r3, addr) \
    asm volatile("ldmatrix.sync.aligned.m8n8.x4.trans.shared.b16 {%0,%1,%2,%3}, [%4];" \
        : "=r"(r0), "=r"(r1), "=r"(r2), "=r"(r3) : "r"(addr))

__device__ __forceinline__ void mma_bf16(float* c, const uint32_t* a,
                                         uint32_t b0, uint32_t b1) {
    asm volatile(
        "mma.sync.aligned.m16n8k16.row.col.f32.bf16.bf16.f32 "
        "{%0,%1,%2,%3}, {%4,%5,%6,%7}, {%8,%9}, {%0,%1,%2,%3};"
        : "+f"(c[0]), "+f"(c[1]), "+f"(c[2]), "+f"(c[3])
        : "r"(a[0]), "r"(a[1]), "r"(a[2]), "r"(a[3]), "r"(b0), "r"(b1));
}
__device__ __forceinline__ void mma_f16(float* c, const uint32_t* a,
                                        uint32_t b0, uint32_t b1) {
    asm volatile(
        "mma.sync.aligned.m16n8k16.row.col.f32.f16.f16.f32 "
        "{%0,%1,%2,%3}, {%4,%5,%6,%7}, {%8,%9}, {%0,%1,%2,%3};"
        : "+f"(c[0]), "+f"(c[1]), "+f"(c[2]), "+f"(c[3])
        : "r"(a[0]), "r"(a[1]), "r"(a[2]), "r"(a[3]), "r"(b0), "r"(b1));
}
__device__ __forceinline__ uint32_t pkb(__nv_bfloat16 a, __nv_bfloat16 b) {
    __nv_bfloat162 t; t.x = a; t.y = b;
    return *(uint32_t*)&t;
}
__device__ __forceinline__ uint32_t pkh(float a, float b) {
    __half2 t = __floats2half2_rn(a, b);
    return *(uint32_t*)&t;
}
// bf16 hi/lo split of 8 floats (GEMM path)
__device__ __forceinline__ void cvt_hl(const float4& f0, const float4& f1,
                                       uint4& h, uint4& l) {
    __nv_bfloat16 h0 = __float2bfloat16_rn(f0.x), h1 = __float2bfloat16_rn(f0.y);
    __nv_bfloat16 h2 = __float2bfloat16_rn(f0.z), h3 = __float2bfloat16_rn(f0.w);
    __nv_bfloat16 h4 = __float2bfloat16_rn(f1.x), h5 = __float2bfloat16_rn(f1.y);
    __nv_bfloat16 h6 = __float2bfloat16_rn(f1.z), h7 = __float2bfloat16_rn(f1.w);
    h.x = pkb(h0, h1); h.y = pkb(h2, h3); h.z = pkb(h4, h5); h.w = pkb(h6, h7);
    float r0 = f0.x - __bfloat162float(h0), r1 = f0.y - __bfloat162float(h1);
    float r2 = f0.z - __bfloat162float(h2), r3 = f0.w - __bfloat162float(h3);
    float r4 = f1.x - __bfloat162float(h4), r5 = f1.y - __bfloat162float(h5);
    float r6 = f1.z - __bfloat162float(h6), r7 = f1.w - __bfloat162float(h7);
    l.x = pkb(__float2bfloat16_rn(r0), __float2bfloat16_rn(r1));
    l.y = pkb(__float2bfloat16_rn(r2), __float2bfloat16_rn(r3));
    l.z = pkb(__float2bfloat16_rn(r4), __float2bfloat16_rn(r5));
    l.w = pkb(__float2bfloat16_rn(r6), __float2bfloat16_rn(r7));
}

// ---------------------------------------------------------------------------
// bf16 split-precision mma GEMM (3-pass hi/lo).
// TGT 0/1: write fp16 to g_qh/g_kh.  TGT 2: write fp16 hi/lo to g_vh/g_vl.
// TGT 3: A = g_av, write fp32 [r][c] to Cout.
// ---------------------------------------------------------------------------
#define GS_STAGE 32768
#define GEMM_SMEM (2 * GS_STAGE)

template <int TGT>
__global__ __launch_bounds__(256) void gemm_bf16s(const float* __restrict__ A,
                                                  const float* __restrict__ Bw,
                                                  const float* __restrict__ bias,
                                                  float* __restrict__ Cout) {
    extern __shared__ char smem[];
    const uint32_t sb = smem_to_u32(smem);
    const int tid = threadIdx.x;
    const int lane = tid & 31;
    const int wid = tid >> 5;
    const int wm = wid & 1;
    const int wn = wid >> 1;
    const int row0 = blockIdx.y * 128;
    const int col0 = blockIdx.x * 128;
    const float* Abase = (TGT == 3) ? (const float*)g_av : A;

    const int pr  = tid >> 1;
    const int pcb = tid & 1;
    const float* gA = Abase + (size_t)(row0 + pr) * 1024 + pcb * 16;
    const float* gB = Bw    + (size_t)(col0 + pr) * 1024 + pcb * 16;

    float4 ra[4], rb[4];
    auto load_regs = [&](int ch) {
        const float* a = gA + ch * 32;
        const float* b = gB + ch * 32;
#pragma unroll
        for (int i = 0; i < 4; i++) {
            ra[i] = *(const float4*)(a + i * 4);
            rb[i] = *(const float4*)(b + i * 4);
        }
    };
    auto store_stage = [&](int buf) {
        char* abase = smem + buf * GS_STAGE + pr * 128;
        char* bbase = abase + 16384;
#pragma unroll
        for (int c = 0; c < 2; c++) {
            int chi = pcb * 2 + c;
            int clo = 4 + chi;
            uint4 h, l;
            cvt_hl(ra[2 * c], ra[2 * c + 1], h, l);
            *(uint4*)(abase + ((chi ^ (pr & 7)) * 16)) = h;
            *(uint4*)(abase + ((clo ^ (pr & 7)) * 16)) = l;
            cvt_hl(rb[2 * c], rb[2 * c + 1], h, l);
            *(uint4*)(bbase + ((chi ^ (pr & 7)) * 16)) = h;
            *(uint4*)(bbase + ((clo ^ (pr & 7)) * 16)) = l;
        }
    };

    float acc[4][4][4];
#pragma unroll
    for (int mt = 0; mt < 4; mt++)
#pragma unroll
        for (int nt = 0; nt < 4; nt++)
#pragma unroll
            for (int i = 0; i < 4; i++) acc[mt][nt][i] = 0.f;

    const int a_rowoff = (lane & 7) + ((lane >> 3) & 1) * 8;
    const int a_csel   = lane >> 4;
    const int b_rowoff = ((lane >> 4) << 3) + (lane & 7);
    const int b_csel   = (lane >> 3) & 1;
    const uint32_t lx = (uint32_t)(lane & 7);

    auto do_mma = [&](int buf) {
        const uint32_t ab = sb + buf * GS_STAGE;
        const uint32_t bb = ab + 16384;
#pragma unroll
        for (int ks = 0; ks < 2; ks++) {
            uint32_t ah[4][4], al[4][4], bh[2][4], bl[2][4];
#pragma unroll
            for (int mt = 0; mt < 4; mt++) {
                int row = wm * 64 + mt * 16 + a_rowoff;
                uint32_t ph = (uint32_t)((ks * 2 + a_csel) ^ lx) * 16;
                LDSM_X4(ah[mt][0], ah[mt][1], ah[mt][2], ah[mt][3],
                        ab + row * 128 + ph);
            }
#pragma unroll
            for (int n2 = 0; n2 < 2; n2++) {
                int row = wn * 32 + n2 * 16 + b_rowoff;
                uint32_t ph = (uint32_t)((ks * 2 + b_csel) ^ lx) * 16;
                LDSM_X4(bh[n2][0], bh[n2][1], bh[n2][2], bh[n2][3],
                        bb + row * 128 + ph);
            }
#pragma unroll
            for (int mt = 0; mt < 4; mt++)
#pragma unroll
                for (int nt = 0; nt < 4; nt++)
                    mma_bf16(acc[mt][nt], ah[mt],
                             bh[nt >> 1][(nt & 1) * 2], bh[nt >> 1][(nt & 1) * 2 + 1]);
#pragma unroll
            for (int n2 = 0; n2 < 2; n2++) {
                int row = wn * 32 + n2 * 16 + b_rowoff;
                uint32_t ph = (uint32_t)((4 + ks * 2 + b_csel) ^ lx) * 16;
                LDSM_X4(bl[n2][0], bl[n2][1], bl[n2][2], bl[n2][3],
                        bb + row * 128 + ph);
            }
#pragma unroll
            for (int mt = 0; mt < 4; mt++)
#pragma unroll
                for (int nt = 0; nt < 4; nt++)
                    mma_bf16(acc[mt][nt], ah[mt],
                             bl[nt >> 1][(nt & 1) * 2], bl[nt >> 1][(nt & 1) * 2 + 1]);
#pragma unroll
            for (int mt = 0; mt < 4; mt++) {
                int row = wm * 64 + mt * 16 + a_rowoff;
                uint32_t ph = (uint32_t)((4 + ks * 2 + a_csel) ^ lx) * 16;
                LDSM_X4(al[mt][0], al[mt][1], al[mt][2], al[mt][3],
                        ab + row * 128 + ph);
            }
#pragma unroll
            for (int mt = 0; mt < 4; mt++)
#pragma unroll
                for (int nt = 0; nt < 4; nt++)
                    mma_bf16(acc[mt][nt], al[mt],
                             bh[nt >> 1][(nt & 1) * 2], bh[nt >> 1][(nt & 1) * 2 + 1]);
        }
    };

    load_regs(0);
    store_stage(0);
    load_regs(1);
    __syncthreads();
    for (int ch = 0; ch < 32; ch++) {
        if (ch + 1 < 32) store_stage((ch + 1) & 1);
        if (ch + 2 < 32) load_regs(ch + 2);
        do_mma(ch & 1);
        __syncthreads();
    }

    const int g = lane >> 2;
    const int cpair = (lane & 3) * 2;
#pragma unroll
    for (int mt = 0; mt < 4; mt++) {
#pragma unroll
        for (int nt = 0; nt < 4; nt++) {
            int col = col0 + wn * 32 + nt * 8 + cpair;
            float2 bi = *(const float2*)(bias + col);
            int r0 = row0 + wm * 64 + mt * 16 + g;
            int r1 = r0 + 8;
            float2 v0 = make_float2(acc[mt][nt][0] + bi.x, acc[mt][nt][1] + bi.y);
            float2 v1 = make_float2(acc[mt][nt][2] + bi.x, acc[mt][nt][3] + bi.y);
            if (TGT == 3) {
                *(float2*)(Cout + (size_t)r0 * 1024 + col) = v0;
                *(float2*)(Cout + (size_t)r1 * 1024 + col) = v1;
            } else {
                int h = col >> 6, d0 = col & 63;
                size_t i0 = (((size_t)((r0 >> 10) * H_ + h)) * W_ + (r0 & 1023)) * D_ + d0;
                size_t i1 = (((size_t)((r1 >> 10) * H_ + h)) * W_ + (r1 & 1023)) * D_ + d0;
                if (TGT == 2) {
                    __half h00 = __float2half_rn(v0.x), h01 = __float2half_rn(v0.y);
                    __half h10 = __float2half_rn(v1.x), h11 = __float2half_rn(v1.y);
                    *(uint32_t*)(g_vh + i0) = pkh(v0.x, v0.y);
                    *(uint32_t*)(g_vh + i1) = pkh(v1.x, v1.y);
                    *(uint32_t*)(g_vl + i0) =
                        pkh(v0.x - __half2float(h00), v0.y - __half2float(h01));
                    *(uint32_t*)(g_vl + i1) =
                        pkh(v1.x - __half2float(h10), v1.y - __half2float(h11));
                } else {
                    __half* dst = (TGT == 0) ? g_qh : g_kh;
                    *(uint32_t*)(dst + i0) = pkh(v0.x, v0.y);
                    *(uint32_t*)(dst + i1) = pkh(v1.x, v1.y);
                }
            }
        }
    }
}

// ---------------------------------------------------------------------------
// Tensor-core flash attention with cp.async double-buffered tiles.
// One CTA per (bh, 128-row w-tile); 8 warps, each owns 16 full rows.
// S[i][j] = ( Qw[i]·Ku[j] + E[i]·Qu[j] ) / 32,  E[i] = er[:, w0+i]
// smem: Qw fp16 [128i][64k]            @ 0       (16KB)
//       Et fp16 [64d][128i]            @ 16384   (16KB)
//       stage s (s=0,1) @ 32768 + s*65536:
//         KQ fp16 [128j][128k]         +0        (32KB)
//         Vhi fp16 [128u][64d]         +32768    (16KB)
//         Vlo fp16 [128u][64d]         +49152    (16KB)
// ---------------------------------------------------------------------------
#define ATTN_SMEM (32768 + 2 * 65536)   // 160KB

__global__ __launch_bounds__(256) void attn_mma(const float* __restrict__ er) {
    extern __shared__ char sm[];
    const uint32_t sb = smem_to_u32(sm);
    const int tid = threadIdx.x;
    const int lane = tid & 31;
    const int warp = tid >> 5;
    const int bh = blockIdx.y;
    const int b = bh >> 4, h = bh & 15;
    const int w0 = blockIdx.x * 128;

    const __half* qbh = g_qh + (size_t)bh * W_ * D_;
    const __half* kbh = g_kh + (size_t)bh * W_ * D_;
    const __half* vhb = g_vh + (size_t)bh * W_ * D_;
    const __half* vlb = g_vl + (size_t)bh * W_ * D_;

    // ---- Qw tile prefetch (once): rows i, 64 fp16 = 128B/row, swizzled
#pragma unroll
    for (int i = 0; i < 4; i++) {
        int idx = tid + i * 256;          // 0..1023
        int r = idx >> 3, c = idx & 7;
        cp_async16(sb + r * 128 + ((c ^ (r & 7)) * 16),
                   qbh + (size_t)(w0 + r) * 64 + c * 8);
    }

    auto prefetch = [&](int ch, int stg) {
        const uint32_t kqb = sb + 32768u + stg * 65536u;
        const uint32_t vbb = kqb + 32768u;
        const __half* ksrc = kbh + (size_t)ch * 128 * 64;
        const __half* qsrc = qbh + (size_t)ch * 128 * 64;
#pragma unroll
        for (int i = 0; i < 8; i++) {
            int idx = tid + i * 256;      // 0..2047
            int j = idx >> 4, c = idx & 15;
            const __half* src = ((c < 8) ? ksrc : qsrc) + j * 64 + (c & 7) * 8;
            cp_async16(kqb + j * 256 + ((c >> 3) * 128) +
                       (((c & 7) ^ (j & 7)) * 16), src);
        }
        const __half* vh = vhb + (size_t)ch * 128 * 64;
        const __half* vl = vlb + (size_t)ch * 128 * 64;
#pragma unroll
        for (int i = 0; i < 8; i++) {
            int idx = tid + i * 256;      // 0..2047
            int pl = idx >> 10, rem = idx & 1023;
            int u = rem >> 3, c = rem & 7;
            const __half* src = (pl ? vl : vh) + u * 64 + c * 8;
            cp_async16(vbb + pl * 16384 + u * 128 + ((c ^ (u & 7)) * 16), src);
        }
    };
    prefetch(0, 0); CP_COMMIT();
    prefetch(1, 1); CP_COMMIT();

    // ---- Et tile (once, manual): Et[d][i] = er[d][w0+i]; rows 256B, swizzled
    for (int t = tid; t < 8192; t += 256) {
        int d = t >> 7, i = t & 127;
        float v = er[d * 1024 + w0 + i];
        int c16 = i >> 3;
        uint32_t addr = 16384u + d * 256 + ((c16 >> 3) * 128) +
                        (((c16 & 7) ^ (d & 7)) * 16) + ((i & 7) * 2);
        *(__half*)(sm + addr) = __float2half_rn(v);
    }

    // per-thread state
    float s[16][4];
    float o[8][4];
    float m0 = -1e30f, m1 = -1e30f, l0 = 0.f, l1 = 0.f;
#pragma unroll
    for (int nt = 0; nt < 8; nt++)
#pragma unroll
        for (int i = 0; i < 4; i++) o[nt][i] = 0.f;

    const int arow = (lane & 7) + ((lane >> 3) & 1) * 8;
    const int acs  = lane >> 4;
    const int brow = ((lane >> 4) << 3) + (lane & 7);
    const int bcs  = (lane >> 3) & 1;
    const int tm = lane >> 3, tr = lane & 7;
    const int i0 = warp * 16;

    for (int ch = 0; ch < 8; ch++) {
        if (ch == 7) { CP_WAIT(0); } else { CP_WAIT(1); }
        __syncthreads();                  // stage ch&1 full (and Qw/Et at ch=0)

        const uint32_t kqb = sb + 32768u + (ch & 1) * 65536u;
        const uint32_t vhs = kqb + 32768u;
        const uint32_t vls = kqb + 49152u;

        // ---- S = [Qw|Et] @ [Ku|Qu]^T   (fp16, K=128)
#pragma unroll
        for (int nt = 0; nt < 16; nt++)
#pragma unroll
            for (int i = 0; i < 4; i++) s[nt][i] = 0.f;

#pragma unroll
        for (int kb = 0; kb < 8; kb++) {
            uint32_t a[4];
            if (kb < 4) {
                int row = i0 + arow;
                int chunk = kb * 2 + acs;
                LDSM_X4(a[0], a[1], a[2], a[3],
                        sb + row * 128 + ((chunk ^ (row & 7)) * 16));
            } else {
                // A-frag trans quadrants: matrix m -> (row = m&1, k = m>>1)
                int d = (kb - 4) * 16 + (tm >> 1) * 8 + tr;
                int icol = i0 + (tm & 1) * 8;
                int c16 = icol >> 3;
                LDSM_X4T(a[0], a[1], a[2], a[3],
                         sb + 16384 + d * 256 + ((c16 >> 3) * 128) +
                         (((c16 & 7) ^ (d & 7)) * 16));
            }
#pragma unroll
            for (int np = 0; np < 8; np++) {
                uint32_t b0, b1, b2, b3;
                int j = np * 16 + brow;
                int chunk = kb * 2 + bcs;
                LDSM_X4(b0, b1, b2, b3,
                        kqb + j * 256 + ((chunk >> 3) * 128) +
                        (((chunk & 7) ^ (j & 7)) * 16));
                mma_f16(s[2 * np], a, b0, b1);
                mma_f16(s[2 * np + 1], a, b2, b3);
            }
        }

        // ---- scale + online softmax (rows g = lane>>2 and g+8)
        float mr0 = -1e30f, mr1 = -1e30f;
#pragma unroll
        for (int nt = 0; nt < 16; nt++) {
            s[nt][0] *= 0.03125f; s[nt][1] *= 0.03125f;
            s[nt][2] *= 0.03125f; s[nt][3] *= 0.03125f;
            mr0 = fmaxf(mr0, fmaxf(s[nt][0], s[nt][1]));
            mr1 = fmaxf(mr1, fmaxf(s[nt][2], s[nt][3]));
        }
        mr0 = fmaxf(mr0, __shfl_xor_sync(0xffffffffu, mr0, 1));
        mr0 = fmaxf(mr0, __shfl_xor_sync(0xffffffffu, mr0, 2));
        mr1 = fmaxf(mr1, __shfl_xor_sync(0xffffffffu, mr1, 1));
        mr1 = fmaxf(mr1, __shfl_xor_sync(0xffffffffu, mr1, 2));
        float mn0 = fmaxf(m0, mr0), mn1 = fmaxf(m1, mr1);
        float c0 = __expf(m0 - mn0), c1 = __expf(m1 - mn1);
        m0 = mn0; m1 = mn1;
        l0 *= c0; l1 *= c1;
#pragma unroll
        for (int nt = 0; nt < 8; nt++) {
            o[nt][0] *= c0; o[nt][1] *= c0;
            o[nt][2] *= c1; o[nt][3] *= c1;
        }
        float rs0 = 0.f, rs1 = 0.f;
#pragma unroll
        for (int nt = 0; nt < 16; nt++) {
            s[nt][0] = __expf(s[nt][0] - mn0);
            s[nt][1] = __expf(s[nt][1] - mn0);
            s[nt][2] = __expf(s[nt][2] - mn1);
            s[nt][3] = __expf(s[nt][3] - mn1);
            rs0 += s[nt][0] + s[nt][1];
            rs1 += s[nt][2] + s[nt][3];
        }
        rs0 += __shfl_xor_sync(0xffffffffu, rs0, 1);
        rs0 += __shfl_xor_sync(0xffffffffu, rs0, 2);
        rs1 += __shfl_xor_sync(0xffffffffu, rs1, 1);
        rs1 += __shfl_xor_sync(0xffffffffu, rs1, 2);
        l0 += rs0; l1 += rs1;

        // ---- O += P @ V  (fp16, 3-pass hi/lo split)
#pragma unroll
        for (int kb = 0; kb < 8; kb++) {
            uint32_t ah[4], al[4];
            {
                float* p0 = s[2 * kb];
                float* p1 = s[2 * kb + 1];
                ah[0] = pkh(p0[0], p0[1]); ah[1] = pkh(p0[2], p0[3]);
                ah[2] = pkh(p1[0], p1[1]); ah[3] = pkh(p1[2], p1[3]);
#pragma unroll
                for (int r = 0; r < 4; r++) {
                    float2 hf = __half22float2(*(__half2*)&ah[r]);
                    float* ps = (r < 2) ? p0 : p1;
                    int c = (r & 1) * 2;
                    al[r] = pkh(ps[c] - hf.x, ps[c + 1] - hf.y);
                }
            }
            int u = kb * 16 + (tm & 1) * 8 + tr;
#pragma unroll
            for (int np = 0; np < 4; np++) {
                int d0 = np * 16 + (tm >> 1) * 8;
                int chunk = d0 >> 3;
                uint32_t off = u * 128 + ((chunk ^ (u & 7)) * 16);
                uint32_t vh0, vh1, vh2, vh3, vl0, vl1, vl2, vl3;
                LDSM_X4T(vh0, vh1, vh2, vh3, vhs + off);
                LDSM_X4T(vl0, vl1, vl2, vl3, vls + off);
                mma_f16(o[2 * np], ah, vh0, vh1);
                mma_f16(o[2 * np + 1], ah, vh2, vh3);
                mma_f16(o[2 * np], al, vh0, vh1);
                mma_f16(o[2 * np + 1], al, vh2, vh3);
                mma_f16(o[2 * np], ah, vl0, vl1);
                mma_f16(o[2 * np + 1], ah, vl2, vl3);
            }
        }

        __syncthreads();                  // stage ch&1 fully consumed
        if (ch + 2 < 8) { prefetch(ch + 2, ch & 1); CP_COMMIT(); }
    }

    // ---- epilogue: normalize, write av [b][w][h*64+d]
    float inv0 = 1.f / l0, inv1 = 1.f / l1;
    const int g = lane >> 2, cp = (lane & 3) * 2;
    const int wr = w0 + warp * 16 + g;
    float* obase = g_av + ((size_t)b * W_ + wr) * C_ + h * 64;
#pragma unroll
    for (int np = 0; np < 8; np++) {
        int d = np * 8 + cp;
        *(float2*)(obase + d) =
            make_float2(o[np][0] * inv0, o[np][1] * inv0);
        *(float2*)(obase + (size_t)8 * C_ + d) =
            make_float2(o[np][2] * inv1, o[np][3] * inv1);
    }
}

// ---------------------------------------------------------------------------
extern "C" void kernel_launch(void* const* d_in, const int* in_sizes, int n_in,
                              void* d_out, int out_size) {
    const float* x  = (const float*)d_in[0];
    const float* Wq = (const float*)d_in[1];
    const float* bq = (const float*)d_in[2];
    const float* Wk = (const float*)d_in[3];
    const float* bk = (const float*)d_in[4];
    const float* Wv = (const float*)d_in[5];
    const float* bv = (const float*)d_in[6];
    const float* Wo = (const float*)d_in[7];
    const float* bo = (const float*)d_in[8];
    const float* er = (const float*)d_in[9];
    float* out = (float*)d_out;

    cudaFuncSetAttribute(gemm_bf16s<0>, cudaFuncAttributeMaxDynamicSharedMemorySize, GEMM_SMEM);
    cudaFuncSetAttribute(gemm_bf16s<1>, cudaFuncAttributeMaxDynamicSharedMemorySize, GEMM_SMEM);
    cudaFuncSetAttribute(gemm_bf16s<2>, cudaFuncAttributeMaxDynamicSharedMemorySize, GEMM_SMEM);
    cudaFuncSetAttribute(gemm_bf16s<3>, cudaFuncAttributeMaxDynamicSharedMemorySize, GEMM_SMEM);
    cudaFuncSetAttribute(attn_mma, cudaFuncAttributeMaxDynamicSharedMemorySize, ATTN_SMEM);

    dim3 g(1024 / 128, 4096 / 128);   // (8, 32)
    gemm_bf16s<0><<<g, 256, GEMM_SMEM>>>(x, Wq, bq, nullptr);
    gemm_bf16s<1><<<g, 256, GEMM_SMEM>>>(x, Wk, bk, nullptr);
    gemm_bf16s<2><<<g, 256, GEMM_SMEM>>>(x, Wv, bv, nullptr);

    attn_mma<<<dim3(8, 64), 256, ATTN_SMEM>>>(er);

    gemm_bf16s<3><<<g, 256, GEMM_SMEM>>>(nullptr, Wo, bo, out);
}